// round 2
// baseline (speedup 1.0000x reference)
#include <cuda_runtime.h>
#include <cuda_bf16.h>
#include <cstdint>

// Problem constants
#define BATCH   1024
#define SEQLEN  128
#define NFEAT   256
#define NHID    30
#define NGATE   120          // 4*NHID
#define MROWS   (BATCH*SEQLEN)   // 131072

// Scratch: precomputed layer-0 input gate pre-activations  xg0[m][g], m = b*128+t
__device__ float g_xg0[(size_t)MROWS * NGATE];

// ---------------------------------------------------------------------------
// Kernel 1: xg0 = x @ w_ih0^T + (b_ih0 + b_hh0)
// M=131072, N=120 (computed as 128 with zero-padded B), K=256
// CTA tile 128x128, K-chunk 32, 256 threads, 8x8 register tile.
// ---------------------------------------------------------------------------
__global__ __launch_bounds__(256) void gemm_xg0(
    const float* __restrict__ x,      // [M,256]
    const float* __restrict__ w,      // [120,256]
    const float* __restrict__ b_ih,   // [120]
    const float* __restrict__ b_hh)   // [120]
{
    __shared__ float As[32][129];   // As[k][m], padded to kill store conflicts
    __shared__ float Bs[32][128];   // Bs[k][n] = w[n][k0+k]

    const int tid = threadIdx.x;
    const int m0  = blockIdx.x * 128;
    const int tx  = tid & 15;      // n-tile index
    const int ty  = tid >> 4;      // m-tile index

    float acc[8][8];
#pragma unroll
    for (int i = 0; i < 8; i++)
#pragma unroll
        for (int j = 0; j < 8; j++) acc[i][j] = 0.0f;

    for (int k0 = 0; k0 < 256; k0 += 32) {
        // Load A tile: 128 rows x 32 cols (float4, 4 per thread)
#pragma unroll
        for (int i = 0; i < 4; i++) {
            int idx = tid + i * 256;          // 0..1023
            int row = idx >> 3;               // 0..127
            int c4  = idx & 7;                // 0..7  (float4 col)
            float4 v = *reinterpret_cast<const float4*>(
                x + (size_t)(m0 + row) * 256 + k0 + c4 * 4);
            As[c4 * 4 + 0][row] = v.x;
            As[c4 * 4 + 1][row] = v.y;
            As[c4 * 4 + 2][row] = v.z;
            As[c4 * 4 + 3][row] = v.w;
        }
        // Load B tile: Bs[k][n] = w[n][k0+k], n>=120 -> 0
#pragma unroll
        for (int i = 0; i < 4; i++) {
            int idx = tid + i * 256;
            int n   = idx >> 3;
            int c4  = idx & 7;
            float4 v = make_float4(0.f, 0.f, 0.f, 0.f);
            if (n < NGATE)
                v = *reinterpret_cast<const float4*>(
                    w + (size_t)n * 256 + k0 + c4 * 4);
            Bs[c4 * 4 + 0][n] = v.x;
            Bs[c4 * 4 + 1][n] = v.y;
            Bs[c4 * 4 + 2][n] = v.z;
            Bs[c4 * 4 + 3][n] = v.w;
        }
        __syncthreads();

#pragma unroll
        for (int kk = 0; kk < 32; kk++) {
            float a[8], bb[8];
#pragma unroll
            for (int i = 0; i < 8; i++) a[i]  = As[kk][ty * 8 + i];
#pragma unroll
            for (int j = 0; j < 8; j++) bb[j] = Bs[kk][tx * 8 + j];
#pragma unroll
            for (int i = 0; i < 8; i++)
#pragma unroll
                for (int j = 0; j < 8; j++)
                    acc[i][j] = fmaf(a[i], bb[j], acc[i][j]);
        }
        __syncthreads();
    }

    // Epilogue: add bias, store only n<120, row-major stride 120
#pragma unroll
    for (int j = 0; j < 8; j++) {
        int n = tx * 8 + j;
        if (n < NGATE) {
            float bias = b_ih[n] + b_hh[n];
#pragma unroll
            for (int i = 0; i < 8; i++) {
                int m = m0 + ty * 8 + i;
                g_xg0[(size_t)m * NGATE + n] = acc[i][j] + bias;
            }
        }
    }
}

// ---------------------------------------------------------------------------
// Kernel 2: fused 2-layer recurrent LSTM + final linear accumulation.
// One CTA (128 threads) per batch element. Thread g<120 owns gate-row g with
// its weight rows held in registers; threads j<30 own the c/h state.
// ---------------------------------------------------------------------------
__device__ __forceinline__ float sig_f(float x) {
    // 1/(1+e^-x); e^|big| -> inf, rcp(inf)=0 -> saturates correctly.
    return __fdividef(1.0f, 1.0f + __expf(-x));
}
__device__ __forceinline__ float tanh_f(float x) {
    // tanh(x) = 2*sigmoid(2x) - 1  (overflow-safe at both ends)
    return fmaf(2.0f, sig_f(2.0f * x), -1.0f);
}

__global__ __launch_bounds__(128) void lstm_rec(
    const float* __restrict__ w_hh0,  // [120,30]
    const float* __restrict__ w_ih1,  // [120,30]
    const float* __restrict__ w_hh1,  // [120,30]
    const float* __restrict__ b_ih1,  // [120]
    const float* __restrict__ b_hh1,  // [120]
    const float* __restrict__ w_lin,  // [3840] (t*30+j)
    const float* __restrict__ b_lin,  // [1]
    float* __restrict__ out)          // [1024]
{
    const int b = blockIdx.x;
    const int g = threadIdx.x;

    __shared__ float sh_h0[NHID];     // layer-0 hidden state
    __shared__ float sh_h1[NHID];     // layer-1 hidden state
    __shared__ float sh_gates[NGATE];

    float wr0[NHID], wiI[NHID], wiH[NHID];
    float bias1 = 0.0f;
    if (g < NGATE) {
#pragma unroll
        for (int k = 0; k < NHID; k++) {
            wr0[k] = w_hh0[g * NHID + k];
            wiI[k] = w_ih1[g * NHID + k];
            wiH[k] = w_hh1[g * NHID + k];
        }
        bias1 = b_ih1[g] + b_hh1[g];
    }

    float c0 = 0.0f, c1 = 0.0f, outacc = 0.0f;
    if (g < NHID) { sh_h0[g] = 0.0f; sh_h1[g] = 0.0f; }
    __syncthreads();

    const float* xg = g_xg0 + (size_t)b * SEQLEN * NGATE;

    for (int t = 0; t < SEQLEN; t++) {
        // --- layer 0 gates ---
        if (g < NGATE) {
            float acc = xg[t * NGATE + g];
#pragma unroll
            for (int k = 0; k < NHID; k++)
                acc = fmaf(sh_h0[k], wr0[k], acc);
            sh_gates[g] = (g >= 60 && g < 90) ? tanh_f(acc) : sig_f(acc);
        }
        __syncthreads();
        // --- layer 0 state update ---
        if (g < NHID) {
            float i  = sh_gates[g];
            float f  = sh_gates[g + 30];
            float gg = sh_gates[g + 60];
            float o  = sh_gates[g + 90];
            c0 = fmaf(f, c0, i * gg);
            sh_h0[g] = o * tanh_f(c0);
        }
        __syncthreads();
        // --- layer 1 gates (input = new sh_h0, recurrent = old sh_h1) ---
        if (g < NGATE) {
            float acc = bias1;
#pragma unroll
            for (int k = 0; k < NHID; k++)
                acc = fmaf(sh_h0[k], wiI[k], fmaf(sh_h1[k], wiH[k], acc));
            sh_gates[g] = (g >= 60 && g < 90) ? tanh_f(acc) : sig_f(acc);
        }
        __syncthreads();
        // --- layer 1 state update + output accumulation ---
        if (g < NHID) {
            float i  = sh_gates[g];
            float f  = sh_gates[g + 30];
            float gg = sh_gates[g + 60];
            float o  = sh_gates[g + 90];
            c1 = fmaf(f, c1, i * gg);
            float h = o * tanh_f(c1);
            sh_h1[g] = h;
            outacc = fmaf(h, w_lin[t * NHID + g], outacc);
        }
        __syncthreads();
    }

    // Reduce outacc across warp 0 (lanes 30,31 hold 0)
    if (g < 32) {
        float v = outacc;
#pragma unroll
        for (int off = 16; off > 0; off >>= 1)
            v += __shfl_down_sync(0xffffffff, v, off);
        if (g == 0) out[b] = v + b_lin[0];
    }
}

// ---------------------------------------------------------------------------
// Entry point
// ---------------------------------------------------------------------------
extern "C" void kernel_launch(void* const* d_in, const int* in_sizes, int n_in,
                              void* d_out, int out_size)
{
    const float* x      = (const float*)d_in[0];
    const float* w_ih0  = (const float*)d_in[1];
    const float* w_hh0  = (const float*)d_in[2];
    const float* b_ih0  = (const float*)d_in[3];
    const float* b_hh0  = (const float*)d_in[4];
    const float* w_ih1  = (const float*)d_in[5];
    const float* w_hh1  = (const float*)d_in[6];
    const float* b_ih1  = (const float*)d_in[7];
    const float* b_hh1  = (const float*)d_in[8];
    const float* w_lin  = (const float*)d_in[9];
    const float* b_lin  = (const float*)d_in[10];
    float* out = (float*)d_out;

    gemm_xg0<<<MROWS / 128, 256>>>(x, w_ih0, b_ih0, b_hh0);
    lstm_rec<<<BATCH, 128>>>(w_hh0, w_ih1, w_hh1, b_ih1, b_hh1, w_lin, b_lin, out);
}

// round 3
// speedup vs baseline: 1.0379x; 1.0379x over previous
#include <cuda_runtime.h>
#include <cuda_bf16.h>
#include <cstdint>

// Problem constants
#define BATCH   1024
#define SEQLEN  128
#define NFEAT   256
#define NHID    30
#define NGATE   120          // 4*NHID
#define MROWS   (BATCH*SEQLEN)   // 131072
#define NB      2            // batch elements per recurrent CTA

// Scratch: precomputed layer-0 input gate pre-activations  xg0[m][g], m = b*128+t
__device__ float g_xg0[(size_t)MROWS * NGATE];

// ---------------------------------------------------------------------------
// Kernel 1: xg0 = x @ w_ih0^T + (b_ih0 + b_hh0)
// M=131072, N=120 (computed as 128 with zero-padded B), K=256
// CTA tile 128x128, K-chunk 32, 256 threads, 8x8 register tile.
// (Measured at ~fp32 FFMA roofline; unchanged this round.)
// ---------------------------------------------------------------------------
__global__ __launch_bounds__(256) void gemm_xg0(
    const float* __restrict__ x,      // [M,256]
    const float* __restrict__ w,      // [120,256]
    const float* __restrict__ b_ih,   // [120]
    const float* __restrict__ b_hh)   // [120]
{
    __shared__ float As[32][129];   // As[k][m], padded to kill store conflicts
    __shared__ float Bs[32][128];   // Bs[k][n] = w[n][k0+k]

    const int tid = threadIdx.x;
    const int m0  = blockIdx.x * 128;
    const int tx  = tid & 15;      // n-tile index
    const int ty  = tid >> 4;      // m-tile index

    float acc[8][8];
#pragma unroll
    for (int i = 0; i < 8; i++)
#pragma unroll
        for (int j = 0; j < 8; j++) acc[i][j] = 0.0f;

    for (int k0 = 0; k0 < 256; k0 += 32) {
#pragma unroll
        for (int i = 0; i < 4; i++) {
            int idx = tid + i * 256;
            int row = idx >> 3;
            int c4  = idx & 7;
            float4 v = *reinterpret_cast<const float4*>(
                x + (size_t)(m0 + row) * 256 + k0 + c4 * 4);
            As[c4 * 4 + 0][row] = v.x;
            As[c4 * 4 + 1][row] = v.y;
            As[c4 * 4 + 2][row] = v.z;
            As[c4 * 4 + 3][row] = v.w;
        }
#pragma unroll
        for (int i = 0; i < 4; i++) {
            int idx = tid + i * 256;
            int n   = idx >> 3;
            int c4  = idx & 7;
            float4 v = make_float4(0.f, 0.f, 0.f, 0.f);
            if (n < NGATE)
                v = *reinterpret_cast<const float4*>(
                    w + (size_t)n * 256 + k0 + c4 * 4);
            Bs[c4 * 4 + 0][n] = v.x;
            Bs[c4 * 4 + 1][n] = v.y;
            Bs[c4 * 4 + 2][n] = v.z;
            Bs[c4 * 4 + 3][n] = v.w;
        }
        __syncthreads();

#pragma unroll
        for (int kk = 0; kk < 32; kk++) {
            float a[8], bb[8];
#pragma unroll
            for (int i = 0; i < 8; i++) a[i]  = As[kk][ty * 8 + i];
#pragma unroll
            for (int j = 0; j < 8; j++) bb[j] = Bs[kk][tx * 8 + j];
#pragma unroll
            for (int i = 0; i < 8; i++)
#pragma unroll
                for (int j = 0; j < 8; j++)
                    acc[i][j] = fmaf(a[i], bb[j], acc[i][j]);
        }
        __syncthreads();
    }

#pragma unroll
    for (int j = 0; j < 8; j++) {
        int n = tx * 8 + j;
        if (n < NGATE) {
            float bias = b_ih[n] + b_hh[n];
#pragma unroll
            for (int i = 0; i < 8; i++) {
                int m = m0 + ty * 8 + i;
                g_xg0[(size_t)m * NGATE + n] = acc[i][j] + bias;
            }
        }
    }
}

// ---------------------------------------------------------------------------
// Kernel 2: fused 2-layer recurrent LSTM + final linear, software-pipelined.
//
// CTA = 256 threads, NB=2 batch elements. Layers skewed in time:
//   iteration p computes layer0 gates for t=p (threads 0..119) and layer1
//   gates for t=p-1 (threads 128..247) in ONE phase, then both state updates
//   (threads 0..119, 2 layers x 2 batch x 30) in a second phase.
//   => 2 barriers/step, 2-way batch ILP in every dot product.
// ---------------------------------------------------------------------------
__device__ __forceinline__ float sig_f(float x) {
    return __fdividef(1.0f, 1.0f + __expf(-x));
}
__device__ __forceinline__ float tanh_f(float x) {
    return fmaf(2.0f, sig_f(2.0f * x), -1.0f);
}

__global__ __launch_bounds__(256) void lstm_rec(
    const float* __restrict__ w_hh0,  // [120,30]
    const float* __restrict__ w_ih1,  // [120,30]
    const float* __restrict__ w_hh1,  // [120,30]
    const float* __restrict__ b_ih1,  // [120]
    const float* __restrict__ b_hh1,  // [120]
    const float* __restrict__ w_lin,  // [3840] (t*30+j)
    const float* __restrict__ b_lin,  // [1]
    float* __restrict__ out)          // [1024]
{
    const int b0  = blockIdx.x * NB;
    const int tid = threadIdx.x;

    __shared__ float sh_h0[NB][32];     // layer-0 hidden state (padded)
    __shared__ float sh_h1[NB][32];     // layer-1 hidden state
    __shared__ float sh_g0[NB][NGATE];  // activated layer-0 gates
    __shared__ float sh_g1[NB][NGATE];  // activated layer-1 gates
    __shared__ float sh_red[NB][NHID];  // output reduction

    const bool is_g0 = (tid < NGATE);                 // layer0 gate threads
    const bool is_g1 = (tid >= 128 && tid < 128 + NGATE); // layer1 gate threads
    const int  g     = is_g1 ? (tid - 128) : tid;

    // Weight registers (role-dependent)
    float w0[NHID], wA[NHID], wB[NHID];
    float bias1 = 0.0f;
    if (is_g0) {
#pragma unroll
        for (int k = 0; k < NHID; k++) w0[k] = w_hh0[g * NHID + k];
    }
    if (is_g1) {
#pragma unroll
        for (int k = 0; k < NHID; k++) {
            wA[k] = w_ih1[g * NHID + k];
            wB[k] = w_hh1[g * NHID + k];
        }
        bias1 = b_ih1[g] + b_hh1[g];
    }

    // Update role: tid < 120 -> (layer uL, batch ubb, hidden uj)
    const int uL  = tid / 60;
    const int ubb = (tid % 60) / 30;
    const int uj  = tid % 30;
    float c = 0.0f, outacc = 0.0f;

    // Init hidden states
    if (tid < NB * 32)       sh_h0[tid / 32][tid % 32] = 0.0f;
    else if (tid < NB * 64)  sh_h1[(tid - NB * 32) / 32][tid % 32] = 0.0f;
    __syncthreads();

    // Prefetch xg(t=0)
    float xg_cur[NB];
    if (is_g0) {
#pragma unroll
        for (int bb = 0; bb < NB; bb++)
            xg_cur[bb] = __ldg(&g_xg0[((size_t)(b0 + bb) * SEQLEN + 0) * NGATE + g]);
    }

    const bool isT = (g >= 60 && g < 90);   // tanh gate group

    for (int p = 0; p <= SEQLEN; p++) {
        // ---------------- gate phase ----------------
        if (is_g0 && p < SEQLEN) {
            float a0 = xg_cur[0];
            float a1 = xg_cur[1];
            // prefetch next timestep (off critical path)
            if (p + 1 < SEQLEN) {
                xg_cur[0] = __ldg(&g_xg0[((size_t)(b0 + 0) * SEQLEN + p + 1) * NGATE + g]);
                xg_cur[1] = __ldg(&g_xg0[((size_t)(b0 + 1) * SEQLEN + p + 1) * NGATE + g]);
            }
#pragma unroll
            for (int k = 0; k < NHID; k++) {
                float h0a = sh_h0[0][k];
                float h0b = sh_h0[1][k];
                a0 = fmaf(h0a, w0[k], a0);
                a1 = fmaf(h0b, w0[k], a1);
            }
            sh_g0[0][g] = isT ? tanh_f(a0) : sig_f(a0);
            sh_g0[1][g] = isT ? tanh_f(a1) : sig_f(a1);
        }
        if (is_g1 && p >= 1) {
            // two parallel accumulators per batch: chain depth 30, 4-way ILP
            float aA0 = bias1, aB0 = 0.0f;
            float aA1 = bias1, aB1 = 0.0f;
#pragma unroll
            for (int k = 0; k < NHID; k++) {
                aA0 = fmaf(sh_h0[0][k], wA[k], aA0);
                aB0 = fmaf(sh_h1[0][k], wB[k], aB0);
                aA1 = fmaf(sh_h0[1][k], wA[k], aA1);
                aB1 = fmaf(sh_h1[1][k], wB[k], aB1);
            }
            float a0 = aA0 + aB0;
            float a1 = aA1 + aB1;
            sh_g1[0][g] = isT ? tanh_f(a0) : sig_f(a0);
            sh_g1[1][g] = isT ? tanh_f(a1) : sig_f(a1);
        }
        __syncthreads();

        // ---------------- update phase ----------------
        if (tid < 2 * NB * NHID) {
            if (uL == 0) {
                if (p < SEQLEN) {
                    float i  = sh_g0[ubb][uj];
                    float f  = sh_g0[ubb][uj + 30];
                    float gg = sh_g0[ubb][uj + 60];
                    float o  = sh_g0[ubb][uj + 90];
                    c = fmaf(f, c, i * gg);
                    sh_h0[ubb][uj] = o * tanh_f(c);
                }
            } else {
                if (p >= 1) {
                    int t = p - 1;
                    float i  = sh_g1[ubb][uj];
                    float f  = sh_g1[ubb][uj + 30];
                    float gg = sh_g1[ubb][uj + 60];
                    float o  = sh_g1[ubb][uj + 90];
                    c = fmaf(f, c, i * gg);
                    float h = o * tanh_f(c);
                    sh_h1[ubb][uj] = h;
                    outacc = fmaf(h, w_lin[t * NHID + uj], outacc);
                }
            }
        }
        __syncthreads();
    }

    // ---------------- output reduction ----------------
    if (tid >= 60 && tid < 120) sh_red[ubb][uj] = outacc;   // uL==1 threads
    __syncthreads();
    if (tid < NB) {
        float s = b_lin[0];
#pragma unroll
        for (int j = 0; j < NHID; j++) s += sh_red[tid][j];
        out[b0 + tid] = s;
    }
}

// ---------------------------------------------------------------------------
// Entry point
// ---------------------------------------------------------------------------
extern "C" void kernel_launch(void* const* d_in, const int* in_sizes, int n_in,
                              void* d_out, int out_size)
{
    const float* x      = (const float*)d_in[0];
    const float* w_ih0  = (const float*)d_in[1];
    const float* w_hh0  = (const float*)d_in[2];
    const float* b_ih0  = (const float*)d_in[3];
    const float* b_hh0  = (const float*)d_in[4];
    const float* w_ih1  = (const float*)d_in[5];
    const float* w_hh1  = (const float*)d_in[6];
    const float* b_ih1  = (const float*)d_in[7];
    const float* b_hh1  = (const float*)d_in[8];
    const float* w_lin  = (const float*)d_in[9];
    const float* b_lin  = (const float*)d_in[10];
    float* out = (float*)d_out;

    gemm_xg0<<<MROWS / 128, 256>>>(x, w_ih0, b_ih0, b_hh0);
    lstm_rec<<<BATCH / NB, 256>>>(w_hh0, w_ih1, w_hh1, b_ih1, b_hh1, w_lin, b_lin, out);
}

// round 4
// speedup vs baseline: 1.2426x; 1.1971x over previous
#include <cuda_runtime.h>
#include <cuda_bf16.h>
#include <cstdint>

// Problem constants
#define BATCH   1024
#define SEQLEN  128
#define NFEAT   256
#define NHID    30
#define NGATE   120          // 4*NHID
#define MROWS   (BATCH*SEQLEN)   // 131072
#define NB      4            // batch elements per recurrent CTA

// Scratch: precomputed layer-0 input gate pre-activations  xg0[m][g], m = b*128+t
__device__ float g_xg0[(size_t)MROWS * NGATE];

// ---------------------------------------------------------------------------
// Kernel 1: xg0 = x @ w_ih0^T + (b_ih0 + b_hh0)
// M=131072, N=120 (computed as 128 with zero-padded B), K=256
// CTA tile 128x128, K-chunk 32, 256 threads, 8x8 register tile.
// (At fp32 FFMA roofline; unchanged this round.)
// ---------------------------------------------------------------------------
__global__ __launch_bounds__(256) void gemm_xg0(
    const float* __restrict__ x,      // [M,256]
    const float* __restrict__ w,      // [120,256]
    const float* __restrict__ b_ih,   // [120]
    const float* __restrict__ b_hh)   // [120]
{
    __shared__ float As[32][129];
    __shared__ float Bs[32][128];

    const int tid = threadIdx.x;
    const int m0  = blockIdx.x * 128;
    const int tx  = tid & 15;
    const int ty  = tid >> 4;

    float acc[8][8];
#pragma unroll
    for (int i = 0; i < 8; i++)
#pragma unroll
        for (int j = 0; j < 8; j++) acc[i][j] = 0.0f;

    for (int k0 = 0; k0 < 256; k0 += 32) {
#pragma unroll
        for (int i = 0; i < 4; i++) {
            int idx = tid + i * 256;
            int row = idx >> 3;
            int c4  = idx & 7;
            float4 v = *reinterpret_cast<const float4*>(
                x + (size_t)(m0 + row) * 256 + k0 + c4 * 4);
            As[c4 * 4 + 0][row] = v.x;
            As[c4 * 4 + 1][row] = v.y;
            As[c4 * 4 + 2][row] = v.z;
            As[c4 * 4 + 3][row] = v.w;
        }
#pragma unroll
        for (int i = 0; i < 4; i++) {
            int idx = tid + i * 256;
            int n   = idx >> 3;
            int c4  = idx & 7;
            float4 v = make_float4(0.f, 0.f, 0.f, 0.f);
            if (n < NGATE)
                v = *reinterpret_cast<const float4*>(
                    w + (size_t)n * 256 + k0 + c4 * 4);
            Bs[c4 * 4 + 0][n] = v.x;
            Bs[c4 * 4 + 1][n] = v.y;
            Bs[c4 * 4 + 2][n] = v.z;
            Bs[c4 * 4 + 3][n] = v.w;
        }
        __syncthreads();

#pragma unroll
        for (int kk = 0; kk < 32; kk++) {
            float a[8], bb[8];
#pragma unroll
            for (int i = 0; i < 8; i++) a[i]  = As[kk][ty * 8 + i];
#pragma unroll
            for (int j = 0; j < 8; j++) bb[j] = Bs[kk][tx * 8 + j];
#pragma unroll
            for (int i = 0; i < 8; i++)
#pragma unroll
                for (int j = 0; j < 8; j++)
                    acc[i][j] = fmaf(a[i], bb[j], acc[i][j]);
        }
        __syncthreads();
    }

#pragma unroll
    for (int j = 0; j < 8; j++) {
        int n = tx * 8 + j;
        if (n < NGATE) {
            float bias = b_ih[n] + b_hh[n];
#pragma unroll
            for (int i = 0; i < 8; i++) {
                int m = m0 + ty * 8 + i;
                g_xg0[(size_t)m * NGATE + n] = acc[i][j] + bias;
            }
        }
    }
}

// ---------------------------------------------------------------------------
// Kernel 2: fused 2-layer recurrent LSTM + final linear.
// NB=4 batch elements per CTA (grid=256 -> single wave at 2 CTAs/SM).
// Hidden states packed as float4 across the 4 batch elements so every dot
// step is one LDS.128 + 4 FFMA (8 independent chains in the layer1 threads).
// Layers skewed in time: 2 barriers per step.
// ---------------------------------------------------------------------------
__device__ __forceinline__ float sig_f(float x) {
    return __fdividef(1.0f, 1.0f + __expf(-x));
}
__device__ __forceinline__ float tanh_f(float x) {
    return fmaf(2.0f, sig_f(2.0f * x), -1.0f);
}

__global__ __launch_bounds__(256, 2) void lstm_rec(
    const float* __restrict__ w_hh0,  // [120,30]
    const float* __restrict__ w_ih1,  // [120,30]
    const float* __restrict__ w_hh1,  // [120,30]
    const float* __restrict__ b_ih1,  // [120]
    const float* __restrict__ b_hh1,  // [120]
    const float* __restrict__ w_lin,  // [3840] (t*30+j)
    const float* __restrict__ b_lin,  // [1]
    float* __restrict__ out)          // [1024]
{
    const int b0  = blockIdx.x * NB;
    const int tid = threadIdx.x;

    __shared__ float4 sh_h0v[NHID];     // component bb = h0 of batch b0+bb
    __shared__ float4 sh_h1v[NHID];
    __shared__ float  sh_g0[NB][NGATE]; // activated layer-0 gates
    __shared__ float  sh_g1[NB][NGATE]; // activated layer-1 gates
    __shared__ float  sh_red[NB][32];

    const bool is_g0 = (tid < NGATE);
    const bool is_g1 = (tid >= 128 && tid < 128 + NGATE);
    const int  g     = is_g1 ? (tid - 128) : tid;

    // Gate-role weights in registers
    float w0[NHID], wA[NHID], wB[NHID];
    float bias1 = 0.0f;
    if (is_g0) {
#pragma unroll
        for (int k = 0; k < NHID; k++) w0[k] = w_hh0[g * NHID + k];
    }
    if (is_g1) {
#pragma unroll
        for (int k = 0; k < NHID; k++) {
            wA[k] = w_ih1[g * NHID + k];
            wB[k] = w_hh1[g * NHID + k];
        }
        bias1 = b_ih1[g] + b_hh1[g];
    }

    // Update role: tid < 240 -> (layer uL, batch ubb, hidden uj)
    const int uL  = tid / (NB * NHID);        // 0 or 1
    const int ur  = tid % (NB * NHID);
    const int ubb = ur / NHID;
    const int uj  = ur % NHID;
    const bool is_upd = (tid < 2 * NB * NHID);
    float c = 0.0f, outacc = 0.0f;

    // Init hidden state
    if (tid < NHID) {
        sh_h0v[tid] = make_float4(0.f, 0.f, 0.f, 0.f);
        sh_h1v[tid] = make_float4(0.f, 0.f, 0.f, 0.f);
    }
    __syncthreads();

    // Prefetch xg(t=0)
    float xg_cur[NB];
    if (is_g0) {
#pragma unroll
        for (int bb = 0; bb < NB; bb++)
            xg_cur[bb] = __ldg(&g_xg0[((size_t)(b0 + bb) * SEQLEN) * NGATE + g]);
    }

    const bool isT = (g >= 60 && g < 90);   // tanh gate group

    for (int p = 0; p <= SEQLEN; p++) {
        // ---------------- gate phase ----------------
        if (is_g0 && p < SEQLEN) {
            float a0 = xg_cur[0], a1 = xg_cur[1], a2 = xg_cur[2], a3 = xg_cur[3];
            if (p + 1 < SEQLEN) {
#pragma unroll
                for (int bb = 0; bb < NB; bb++)
                    xg_cur[bb] = __ldg(&g_xg0[((size_t)(b0 + bb) * SEQLEN + p + 1) * NGATE + g]);
            }
#pragma unroll
            for (int k = 0; k < NHID; k++) {
                float4 h = sh_h0v[k];
                float  w = w0[k];
                a0 = fmaf(h.x, w, a0);
                a1 = fmaf(h.y, w, a1);
                a2 = fmaf(h.z, w, a2);
                a3 = fmaf(h.w, w, a3);
            }
            if (isT) {
                sh_g0[0][g] = tanh_f(a0); sh_g0[1][g] = tanh_f(a1);
                sh_g0[2][g] = tanh_f(a2); sh_g0[3][g] = tanh_f(a3);
            } else {
                sh_g0[0][g] = sig_f(a0); sh_g0[1][g] = sig_f(a1);
                sh_g0[2][g] = sig_f(a2); sh_g0[3][g] = sig_f(a3);
            }
        }
        if (is_g1 && p >= 1) {
            float aA0 = bias1, aA1 = bias1, aA2 = bias1, aA3 = bias1;
            float aB0 = 0.f, aB1 = 0.f, aB2 = 0.f, aB3 = 0.f;
#pragma unroll
            for (int k = 0; k < NHID; k++) {
                float4 h0 = sh_h0v[k];
                float4 h1 = sh_h1v[k];
                float  wa = wA[k], wb = wB[k];
                aA0 = fmaf(h0.x, wa, aA0);
                aA1 = fmaf(h0.y, wa, aA1);
                aA2 = fmaf(h0.z, wa, aA2);
                aA3 = fmaf(h0.w, wa, aA3);
                aB0 = fmaf(h1.x, wb, aB0);
                aB1 = fmaf(h1.y, wb, aB1);
                aB2 = fmaf(h1.z, wb, aB2);
                aB3 = fmaf(h1.w, wb, aB3);
            }
            float a0 = aA0 + aB0, a1 = aA1 + aB1, a2 = aA2 + aB2, a3 = aA3 + aB3;
            if (isT) {
                sh_g1[0][g] = tanh_f(a0); sh_g1[1][g] = tanh_f(a1);
                sh_g1[2][g] = tanh_f(a2); sh_g1[3][g] = tanh_f(a3);
            } else {
                sh_g1[0][g] = sig_f(a0); sh_g1[1][g] = sig_f(a1);
                sh_g1[2][g] = sig_f(a2); sh_g1[3][g] = sig_f(a3);
            }
        }
        __syncthreads();

        // ---------------- update phase ----------------
        if (is_upd) {
            if (uL == 0) {
                if (p < SEQLEN) {
                    float i  = sh_g0[ubb][uj];
                    float f  = sh_g0[ubb][uj + 30];
                    float gg = sh_g0[ubb][uj + 60];
                    float o  = sh_g0[ubb][uj + 90];
                    c = fmaf(f, c, i * gg);
                    float h = o * tanh_f(c);
                    ((float*)&sh_h0v[uj])[ubb] = h;
                }
            } else {
                if (p >= 1) {
                    int t = p - 1;
                    float i  = sh_g1[ubb][uj];
                    float f  = sh_g1[ubb][uj + 30];
                    float gg = sh_g1[ubb][uj + 60];
                    float o  = sh_g1[ubb][uj + 90];
                    c = fmaf(f, c, i * gg);
                    float h = o * tanh_f(c);
                    ((float*)&sh_h1v[uj])[ubb] = h;
                    outacc = fmaf(h, w_lin[t * NHID + uj], outacc);
                }
            }
        }
        __syncthreads();
    }

    // ---------------- output reduction ----------------
    if (is_upd && uL == 1) sh_red[ubb][uj] = outacc;
    __syncthreads();
    if (tid < NB) {
        float s = b_lin[0];
#pragma unroll
        for (int j = 0; j < NHID; j++) s += sh_red[tid][j];
        out[b0 + tid] = s;
    }
}

// ---------------------------------------------------------------------------
// Entry point
// ---------------------------------------------------------------------------
extern "C" void kernel_launch(void* const* d_in, const int* in_sizes, int n_in,
                              void* d_out, int out_size)
{
    const float* x      = (const float*)d_in[0];
    const float* w_ih0  = (const float*)d_in[1];
    const float* w_hh0  = (const float*)d_in[2];
    const float* b_ih0  = (const float*)d_in[3];
    const float* b_hh0  = (const float*)d_in[4];
    const float* w_ih1  = (const float*)d_in[5];
    const float* w_hh1  = (const float*)d_in[6];
    const float* b_ih1  = (const float*)d_in[7];
    const float* b_hh1  = (const float*)d_in[8];
    const float* w_lin  = (const float*)d_in[9];
    const float* b_lin  = (const float*)d_in[10];
    float* out = (float*)d_out;

    gemm_xg0<<<MROWS / 128, 256>>>(x, w_ih0, b_ih0, b_hh0);
    lstm_rec<<<BATCH / NB, 256>>>(w_hh0, w_ih1, w_hh1, b_ih1, b_hh1, w_lin, b_lin, out);
}

// round 5
// speedup vs baseline: 1.6534x; 1.3306x over previous
#include <cuda_runtime.h>
#include <cuda_bf16.h>
#include <cstdint>

// Problem constants
#define BATCH   1024
#define SEQLEN  128
#define NFEAT   256
#define NHID    30
#define NGATE   120          // 4*NHID
#define MROWS   (BATCH*SEQLEN)   // 131072
#define NB      4            // batch elements per recurrent CTA

// Scratch: precomputed layer-0 input gate pre-activations  xg0[m][g], m = b*128+t
__device__ float g_xg0[(size_t)MROWS * NGATE];

// ---------------------------------------------------------------------------
// Kernel 1: xg0 = x @ w_ih0^T + (b_ih0 + b_hh0)   -- tensor-core split-bf16
// M=131072, N=120 (padded 128), K=256.
// Each fp32 value v = hi + lo (two bf16); D = Ahi*Bhi + Ahi*Blo + Alo*Bhi.
// CTA tile 128x128, K-chunk 32, 256 threads (8 warps, 64x32 warp tiles),
// mma.sync.m16n8k16.bf16 with fp32 accumulators.
// ---------------------------------------------------------------------------
#define BK     32
#define SAS    40              // smem row stride in bf16 (32 + 8 pad -> conflict-free)

__device__ __forceinline__ uint32_t smem_u32(const void* p) {
    return (uint32_t)__cvta_generic_to_shared(p);
}

__device__ __forceinline__ void ldm_x4(uint32_t addr, uint32_t& r0, uint32_t& r1,
                                       uint32_t& r2, uint32_t& r3) {
    asm volatile("ldmatrix.sync.aligned.m8n8.x4.shared.b16 {%0,%1,%2,%3}, [%4];"
                 : "=r"(r0), "=r"(r1), "=r"(r2), "=r"(r3) : "r"(addr));
}
__device__ __forceinline__ void ldm_x2(uint32_t addr, uint32_t& r0, uint32_t& r1) {
    asm volatile("ldmatrix.sync.aligned.m8n8.x2.shared.b16 {%0,%1}, [%2];"
                 : "=r"(r0), "=r"(r1) : "r"(addr));
}
__device__ __forceinline__ void mma_bf16(float* c, const uint32_t* a, const uint32_t* b) {
    asm volatile(
        "mma.sync.aligned.m16n8k16.row.col.f32.bf16.bf16.f32 "
        "{%0,%1,%2,%3}, {%4,%5,%6,%7}, {%8,%9}, {%0,%1,%2,%3};"
        : "+f"(c[0]), "+f"(c[1]), "+f"(c[2]), "+f"(c[3])
        : "r"(a[0]), "r"(a[1]), "r"(a[2]), "r"(a[3]), "r"(b[0]), "r"(b[1]));
}

__global__ __launch_bounds__(256) void gemm_xg0_tc(
    const float* __restrict__ x,      // [M,256]
    const float* __restrict__ w,      // [120,256]
    const float* __restrict__ b_ih,   // [120]
    const float* __restrict__ b_hh)   // [120]
{
    __shared__ __nv_bfloat16 sAhi[128 * SAS];
    __shared__ __nv_bfloat16 sAlo[128 * SAS];
    __shared__ __nv_bfloat16 sBhi[128 * SAS];
    __shared__ __nv_bfloat16 sBlo[128 * SAS];

    const int tid  = threadIdx.x;
    const int lane = tid & 31;
    const int wid  = tid >> 5;
    const int m0   = blockIdx.x * 128;

    // Warp tile: 64(m) x 32(n). wm in {0,1}, wn in {0..3}
    const int wm = wid & 1;
    const int wn = wid >> 1;
    const int warp_m = wm * 64;
    const int warp_n = wn * 32;

    float acc[4][4][4];
#pragma unroll
    for (int i = 0; i < 4; i++)
#pragma unroll
        for (int j = 0; j < 4; j++)
#pragma unroll
            for (int k = 0; k < 4; k++) acc[i][j][k] = 0.0f;

    // Precompute ldmatrix lane addresses (offsets within smem tiles)
    // A (.x4): matrix idx = lane/8 -> m += ((idx&1)*8), k += ((idx>>1)*8)
    const int a_mo = (lane & 7) + ((lane >> 3) & 1) * 8;
    const int a_ko = ((lane >> 4) & 1) * 8;
    // B (.x2): lanes 0-7 -> (n0+l, k), lanes 8-15 -> (n0+l-8, k+8)
    const int bl   = lane & 15;
    const int b_no = bl & 7;
    const int b_ko = ((bl >> 3) & 1) * 8;

    for (int k0 = 0; k0 < NFEAT; k0 += BK) {
        // ---- load + convert A tile: 128 rows x 32 cols fp32 -> hi/lo bf16
#pragma unroll
        for (int i = 0; i < 4; i++) {
            int idx = tid + i * 256;        // 0..1023 float4 slots
            int row = idx >> 3;             // 0..127
            int c4  = idx & 7;              // 0..7
            float4 v = *reinterpret_cast<const float4*>(
                x + (size_t)(m0 + row) * NFEAT + k0 + c4 * 4);
            float vs[4] = {v.x, v.y, v.z, v.w};
#pragma unroll
            for (int j = 0; j < 4; j++) {
                __nv_bfloat16 h = __float2bfloat16(vs[j]);
                __nv_bfloat16 l = __float2bfloat16(vs[j] - __bfloat162float(h));
                sAhi[row * SAS + c4 * 4 + j] = h;
                sAlo[row * SAS + c4 * 4 + j] = l;
            }
        }
        // ---- load + convert B tile: rows n (0..127, >=120 zero) x 32 cols
#pragma unroll
        for (int i = 0; i < 4; i++) {
            int idx = tid + i * 256;
            int n   = idx >> 3;
            int c4  = idx & 7;
            float4 v = make_float4(0.f, 0.f, 0.f, 0.f);
            if (n < NGATE)
                v = *reinterpret_cast<const float4*>(
                    w + (size_t)n * NFEAT + k0 + c4 * 4);
            float vs[4] = {v.x, v.y, v.z, v.w};
#pragma unroll
            for (int j = 0; j < 4; j++) {
                __nv_bfloat16 h = __float2bfloat16(vs[j]);
                __nv_bfloat16 l = __float2bfloat16(vs[j] - __bfloat162float(h));
                sBhi[n * SAS + c4 * 4 + j] = h;
                sBlo[n * SAS + c4 * 4 + j] = l;
            }
        }
        __syncthreads();

        // ---- compute: 2 k16-steps per chunk
#pragma unroll
        for (int ks = 0; ks < BK; ks += 16) {
            uint32_t ahi[4][4], alo[4][4], bhi[4][2], blo[4][2];
#pragma unroll
            for (int mi = 0; mi < 4; mi++) {
                int mrow = warp_m + mi * 16 + a_mo;
                int kcol = ks + a_ko;
                ldm_x4(smem_u32(&sAhi[mrow * SAS + kcol]),
                       ahi[mi][0], ahi[mi][1], ahi[mi][2], ahi[mi][3]);
                ldm_x4(smem_u32(&sAlo[mrow * SAS + kcol]),
                       alo[mi][0], alo[mi][1], alo[mi][2], alo[mi][3]);
            }
#pragma unroll
            for (int ni = 0; ni < 4; ni++) {
                int nrow = warp_n + ni * 8 + b_no;
                int kcol = ks + b_ko;
                ldm_x2(smem_u32(&sBhi[nrow * SAS + kcol]), bhi[ni][0], bhi[ni][1]);
                ldm_x2(smem_u32(&sBlo[nrow * SAS + kcol]), blo[ni][0], blo[ni][1]);
            }
#pragma unroll
            for (int mi = 0; mi < 4; mi++)
#pragma unroll
                for (int ni = 0; ni < 4; ni++) {
                    mma_bf16(acc[mi][ni], ahi[mi], bhi[ni]);
                    mma_bf16(acc[mi][ni], ahi[mi], blo[ni]);
                    mma_bf16(acc[mi][ni], alo[mi], bhi[ni]);
                }
        }
        __syncthreads();
    }

    // ---- epilogue: add bias, store n<120, row-major stride 120
    const int gid  = lane >> 2;     // groupID
    const int tig  = lane & 3;
#pragma unroll
    for (int ni = 0; ni < 4; ni++) {
        int col = warp_n + ni * 8 + tig * 2;
        float bias0 = 0.f, bias1 = 0.f;
        if (col < NGATE)     bias0 = b_ih[col] + b_hh[col];
        if (col + 1 < NGATE) bias1 = b_ih[col + 1] + b_hh[col + 1];
#pragma unroll
        for (int mi = 0; mi < 4; mi++) {
            int row = m0 + warp_m + mi * 16 + gid;
            float* c = acc[mi][ni];
            if (col < NGATE) {
                g_xg0[(size_t)row * NGATE + col]       = c[0] + bias0;
                g_xg0[(size_t)(row + 8) * NGATE + col] = c[2] + bias0;
            }
            if (col + 1 < NGATE) {
                g_xg0[(size_t)row * NGATE + col + 1]       = c[1] + bias1;
                g_xg0[(size_t)(row + 8) * NGATE + col + 1] = c[3] + bias1;
            }
        }
    }
}

// ---------------------------------------------------------------------------
// Kernel 2: fused 2-layer recurrent LSTM + final linear. (unchanged, 175us)
// ---------------------------------------------------------------------------
__device__ __forceinline__ float sig_f(float x) {
    return __fdividef(1.0f, 1.0f + __expf(-x));
}
__device__ __forceinline__ float tanh_f(float x) {
    return fmaf(2.0f, sig_f(2.0f * x), -1.0f);
}

__global__ __launch_bounds__(256, 2) void lstm_rec(
    const float* __restrict__ w_hh0,  // [120,30]
    const float* __restrict__ w_ih1,  // [120,30]
    const float* __restrict__ w_hh1,  // [120,30]
    const float* __restrict__ b_ih1,  // [120]
    const float* __restrict__ b_hh1,  // [120]
    const float* __restrict__ w_lin,  // [3840] (t*30+j)
    const float* __restrict__ b_lin,  // [1]
    float* __restrict__ out)          // [1024]
{
    const int b0  = blockIdx.x * NB;
    const int tid = threadIdx.x;

    __shared__ float4 sh_h0v[NHID];
    __shared__ float4 sh_h1v[NHID];
    __shared__ float  sh_g0[NB][NGATE];
    __shared__ float  sh_g1[NB][NGATE];
    __shared__ float  sh_red[NB][32];

    const bool is_g0 = (tid < NGATE);
    const bool is_g1 = (tid >= 128 && tid < 128 + NGATE);
    const int  g     = is_g1 ? (tid - 128) : tid;

    float w0[NHID], wA[NHID], wB[NHID];
    float bias1 = 0.0f;
    if (is_g0) {
#pragma unroll
        for (int k = 0; k < NHID; k++) w0[k] = w_hh0[g * NHID + k];
    }
    if (is_g1) {
#pragma unroll
        for (int k = 0; k < NHID; k++) {
            wA[k] = w_ih1[g * NHID + k];
            wB[k] = w_hh1[g * NHID + k];
        }
        bias1 = b_ih1[g] + b_hh1[g];
    }

    const int uL  = tid / (NB * NHID);
    const int ur  = tid % (NB * NHID);
    const int ubb = ur / NHID;
    const int uj  = ur % NHID;
    const bool is_upd = (tid < 2 * NB * NHID);
    float c = 0.0f, outacc = 0.0f;

    if (tid < NHID) {
        sh_h0v[tid] = make_float4(0.f, 0.f, 0.f, 0.f);
        sh_h1v[tid] = make_float4(0.f, 0.f, 0.f, 0.f);
    }
    __syncthreads();

    float xg_cur[NB];
    if (is_g0) {
#pragma unroll
        for (int bb = 0; bb < NB; bb++)
            xg_cur[bb] = __ldg(&g_xg0[((size_t)(b0 + bb) * SEQLEN) * NGATE + g]);
    }

    const bool isT = (g >= 60 && g < 90);

    for (int p = 0; p <= SEQLEN; p++) {
        if (is_g0 && p < SEQLEN) {
            float a0 = xg_cur[0], a1 = xg_cur[1], a2 = xg_cur[2], a3 = xg_cur[3];
            if (p + 1 < SEQLEN) {
#pragma unroll
                for (int bb = 0; bb < NB; bb++)
                    xg_cur[bb] = __ldg(&g_xg0[((size_t)(b0 + bb) * SEQLEN + p + 1) * NGATE + g]);
            }
#pragma unroll
            for (int k = 0; k < NHID; k++) {
                float4 h = sh_h0v[k];
                float  w = w0[k];
                a0 = fmaf(h.x, w, a0);
                a1 = fmaf(h.y, w, a1);
                a2 = fmaf(h.z, w, a2);
                a3 = fmaf(h.w, w, a3);
            }
            if (isT) {
                sh_g0[0][g] = tanh_f(a0); sh_g0[1][g] = tanh_f(a1);
                sh_g0[2][g] = tanh_f(a2); sh_g0[3][g] = tanh_f(a3);
            } else {
                sh_g0[0][g] = sig_f(a0); sh_g0[1][g] = sig_f(a1);
                sh_g0[2][g] = sig_f(a2); sh_g0[3][g] = sig_f(a3);
            }
        }
        if (is_g1 && p >= 1) {
            float aA0 = bias1, aA1 = bias1, aA2 = bias1, aA3 = bias1;
            float aB0 = 0.f, aB1 = 0.f, aB2 = 0.f, aB3 = 0.f;
#pragma unroll
            for (int k = 0; k < NHID; k++) {
                float4 h0 = sh_h0v[k];
                float4 h1 = sh_h1v[k];
                float  wa = wA[k], wb = wB[k];
                aA0 = fmaf(h0.x, wa, aA0);
                aA1 = fmaf(h0.y, wa, aA1);
                aA2 = fmaf(h0.z, wa, aA2);
                aA3 = fmaf(h0.w, wa, aA3);
                aB0 = fmaf(h1.x, wb, aB0);
                aB1 = fmaf(h1.y, wb, aB1);
                aB2 = fmaf(h1.z, wb, aB2);
                aB3 = fmaf(h1.w, wb, aB3);
            }
            float a0 = aA0 + aB0, a1 = aA1 + aB1, a2 = aA2 + aB2, a3 = aA3 + aB3;
            if (isT) {
                sh_g1[0][g] = tanh_f(a0); sh_g1[1][g] = tanh_f(a1);
                sh_g1[2][g] = tanh_f(a2); sh_g1[3][g] = tanh_f(a3);
            } else {
                sh_g1[0][g] = sig_f(a0); sh_g1[1][g] = sig_f(a1);
                sh_g1[2][g] = sig_f(a2); sh_g1[3][g] = sig_f(a3);
            }
        }
        __syncthreads();

        if (is_upd) {
            if (uL == 0) {
                if (p < SEQLEN) {
                    float i  = sh_g0[ubb][uj];
                    float f  = sh_g0[ubb][uj + 30];
                    float gg = sh_g0[ubb][uj + 60];
                    float o  = sh_g0[ubb][uj + 90];
                    c = fmaf(f, c, i * gg);
                    float h = o * tanh_f(c);
                    ((float*)&sh_h0v[uj])[ubb] = h;
                }
            } else {
                if (p >= 1) {
                    int t = p - 1;
                    float i  = sh_g1[ubb][uj];
                    float f  = sh_g1[ubb][uj + 30];
                    float gg = sh_g1[ubb][uj + 60];
                    float o  = sh_g1[ubb][uj + 90];
                    c = fmaf(f, c, i * gg);
                    float h = o * tanh_f(c);
                    ((float*)&sh_h1v[uj])[ubb] = h;
                    outacc = fmaf(h, w_lin[t * NHID + uj], outacc);
                }
            }
        }
        __syncthreads();
    }

    if (is_upd && uL == 1) sh_red[ubb][uj] = outacc;
    __syncthreads();
    if (tid < NB) {
        float s = b_lin[0];
#pragma unroll
        for (int j = 0; j < NHID; j++) s += sh_red[tid][j];
        out[b0 + tid] = s;
    }
}

// ---------------------------------------------------------------------------
// Entry point
// ---------------------------------------------------------------------------
extern "C" void kernel_launch(void* const* d_in, const int* in_sizes, int n_in,
                              void* d_out, int out_size)
{
    const float* x      = (const float*)d_in[0];
    const float* w_ih0  = (const float*)d_in[1];
    const float* w_hh0  = (const float*)d_in[2];
    const float* b_ih0  = (const float*)d_in[3];
    const float* b_hh0  = (const float*)d_in[4];
    const float* w_ih1  = (const float*)d_in[5];
    const float* w_hh1  = (const float*)d_in[6];
    const float* b_ih1  = (const float*)d_in[7];
    const float* b_hh1  = (const float*)d_in[8];
    const float* w_lin  = (const float*)d_in[9];
    const float* b_lin  = (const float*)d_in[10];
    float* out = (float*)d_out;

    gemm_xg0_tc<<<MROWS / 128, 256>>>(x, w_ih0, b_ih0, b_hh0);
    lstm_rec<<<BATCH / NB, 256>>>(w_hh0, w_ih1, w_hh1, b_ih1, b_hh1, w_lin, b_lin, out);
}

// round 6
// speedup vs baseline: 1.8027x; 1.0903x over previous
#include <cuda_runtime.h>
#include <cuda_bf16.h>
#include <cstdint>

// Problem constants
#define BATCH   1024
#define SEQLEN  128
#define NFEAT   256
#define NHID    30
#define NGATE   120          // 4*NHID
#define MROWS   (BATCH*SEQLEN)   // 131072
#define NB      4            // batch elements per recurrent CTA

// Scratch: precomputed layer-0 input gate pre-activations  xg0[m][g], m = b*128+t
__device__ float g_xg0[(size_t)MROWS * NGATE];

// ---------------------------------------------------------------------------
// Kernel 1: xg0 = x @ w_ih0^T + (b_ih0 + b_hh0)   -- tensor-core split-bf16
// v = hi(trunc bf16) + lo(bf16);  D = Ahi*Bhi + Ahi*Blo + Alo*Bhi.
// Packed conversion: PRMT for hi pairs, CVT.bf16x2 for lo pairs, STS.64.
// ---------------------------------------------------------------------------
#define BK     32
#define SAS    40              // smem row stride in bf16 (conflict-free for ldmatrix)

__device__ __forceinline__ uint32_t smem_u32(const void* p) {
    return (uint32_t)__cvta_generic_to_shared(p);
}
__device__ __forceinline__ void ldm_x4(uint32_t addr, uint32_t& r0, uint32_t& r1,
                                       uint32_t& r2, uint32_t& r3) {
    asm volatile("ldmatrix.sync.aligned.m8n8.x4.shared.b16 {%0,%1,%2,%3}, [%4];"
                 : "=r"(r0), "=r"(r1), "=r"(r2), "=r"(r3) : "r"(addr));
}
__device__ __forceinline__ void ldm_x2(uint32_t addr, uint32_t& r0, uint32_t& r1) {
    asm volatile("ldmatrix.sync.aligned.m8n8.x2.shared.b16 {%0,%1}, [%2];"
                 : "=r"(r0), "=r"(r1) : "r"(addr));
}
__device__ __forceinline__ void mma_bf16(float* c, const uint32_t* a, const uint32_t* b) {
    asm volatile(
        "mma.sync.aligned.m16n8k16.row.col.f32.bf16.bf16.f32 "
        "{%0,%1,%2,%3}, {%4,%5,%6,%7}, {%8,%9}, {%0,%1,%2,%3};"
        : "+f"(c[0]), "+f"(c[1]), "+f"(c[2]), "+f"(c[3])
        : "r"(a[0]), "r"(a[1]), "r"(a[2]), "r"(a[3]), "r"(b[0]), "r"(b[1]));
}

// Convert float4 -> packed hi (trunc) + packed lo (residual, rn)
__device__ __forceinline__ void cvt_hilo(float4 v, uint2& hi, uint2& lo) {
    uint32_t bx = __float_as_uint(v.x), by = __float_as_uint(v.y);
    uint32_t bz = __float_as_uint(v.z), bw = __float_as_uint(v.w);
    hi.x = __byte_perm(bx, by, 0x7632);
    hi.y = __byte_perm(bz, bw, 0x7632);
    float lx = v.x - __uint_as_float(bx & 0xffff0000u);
    float ly = v.y - __uint_as_float(by & 0xffff0000u);
    float lz = v.z - __uint_as_float(bz & 0xffff0000u);
    float lw = v.w - __uint_as_float(bw & 0xffff0000u);
    __nv_bfloat162 l01 = __floats2bfloat162_rn(lx, ly);
    __nv_bfloat162 l23 = __floats2bfloat162_rn(lz, lw);
    lo.x = *reinterpret_cast<uint32_t*>(&l01);
    lo.y = *reinterpret_cast<uint32_t*>(&l23);
}

__global__ __launch_bounds__(256) void gemm_xg0_tc(
    const float* __restrict__ x,      // [M,256]
    const float* __restrict__ w,      // [120,256]
    const float* __restrict__ b_ih,   // [120]
    const float* __restrict__ b_hh)   // [120]
{
    __shared__ __nv_bfloat16 sAhi[128 * SAS];
    __shared__ __nv_bfloat16 sAlo[128 * SAS];
    __shared__ __nv_bfloat16 sBhi[128 * SAS];
    __shared__ __nv_bfloat16 sBlo[128 * SAS];

    const int tid  = threadIdx.x;
    const int lane = tid & 31;
    const int wid  = tid >> 5;
    const int m0   = blockIdx.x * 128;

    const int wm = wid & 1;
    const int wn = wid >> 1;
    const int warp_m = wm * 64;
    const int warp_n = wn * 32;

    float acc[4][4][4];
#pragma unroll
    for (int i = 0; i < 4; i++)
#pragma unroll
        for (int j = 0; j < 4; j++)
#pragma unroll
            for (int k = 0; k < 4; k++) acc[i][j][k] = 0.0f;

    const int a_mo = (lane & 7) + ((lane >> 3) & 1) * 8;
    const int a_ko = ((lane >> 4) & 1) * 8;
    const int bl   = lane & 15;
    const int b_no = bl & 7;
    const int b_ko = ((bl >> 3) & 1) * 8;

    for (int k0 = 0; k0 < NFEAT; k0 += BK) {
#pragma unroll
        for (int i = 0; i < 4; i++) {
            int idx = tid + i * 256;
            int row = idx >> 3;
            int c4  = idx & 7;
            float4 v = *reinterpret_cast<const float4*>(
                x + (size_t)(m0 + row) * NFEAT + k0 + c4 * 4);
            uint2 hi, lo;
            cvt_hilo(v, hi, lo);
            *reinterpret_cast<uint2*>(&sAhi[row * SAS + c4 * 4]) = hi;
            *reinterpret_cast<uint2*>(&sAlo[row * SAS + c4 * 4]) = lo;
        }
#pragma unroll
        for (int i = 0; i < 4; i++) {
            int idx = tid + i * 256;
            int n   = idx >> 3;
            int c4  = idx & 7;
            float4 v = make_float4(0.f, 0.f, 0.f, 0.f);
            if (n < NGATE)
                v = *reinterpret_cast<const float4*>(
                    w + (size_t)n * NFEAT + k0 + c4 * 4);
            uint2 hi, lo;
            cvt_hilo(v, hi, lo);
            *reinterpret_cast<uint2*>(&sBhi[n * SAS + c4 * 4]) = hi;
            *reinterpret_cast<uint2*>(&sBlo[n * SAS + c4 * 4]) = lo;
        }
        __syncthreads();

#pragma unroll
        for (int ks = 0; ks < BK; ks += 16) {
            uint32_t ahi[4][4], alo[4][4], bhi[4][2], blo[4][2];
#pragma unroll
            for (int mi = 0; mi < 4; mi++) {
                int mrow = warp_m + mi * 16 + a_mo;
                int kcol = ks + a_ko;
                ldm_x4(smem_u32(&sAhi[mrow * SAS + kcol]),
                       ahi[mi][0], ahi[mi][1], ahi[mi][2], ahi[mi][3]);
                ldm_x4(smem_u32(&sAlo[mrow * SAS + kcol]),
                       alo[mi][0], alo[mi][1], alo[mi][2], alo[mi][3]);
            }
#pragma unroll
            for (int ni = 0; ni < 4; ni++) {
                int nrow = warp_n + ni * 8 + b_no;
                int kcol = ks + b_ko;
                ldm_x2(smem_u32(&sBhi[nrow * SAS + kcol]), bhi[ni][0], bhi[ni][1]);
                ldm_x2(smem_u32(&sBlo[nrow * SAS + kcol]), blo[ni][0], blo[ni][1]);
            }
#pragma unroll
            for (int mi = 0; mi < 4; mi++)
#pragma unroll
                for (int ni = 0; ni < 4; ni++) {
                    mma_bf16(acc[mi][ni], ahi[mi], bhi[ni]);
                    mma_bf16(acc[mi][ni], ahi[mi], blo[ni]);
                    mma_bf16(acc[mi][ni], alo[mi], bhi[ni]);
                }
        }
        __syncthreads();
    }

    const int gid  = lane >> 2;
    const int tig  = lane & 3;
#pragma unroll
    for (int ni = 0; ni < 4; ni++) {
        int col = warp_n + ni * 8 + tig * 2;
        float bias0 = 0.f, bias1 = 0.f;
        if (col < NGATE)     bias0 = b_ih[col] + b_hh[col];
        if (col + 1 < NGATE) bias1 = b_ih[col + 1] + b_hh[col + 1];
#pragma unroll
        for (int mi = 0; mi < 4; mi++) {
            int row = m0 + warp_m + mi * 16 + gid;
            float* c = acc[mi][ni];
            if (col < NGATE) {
                g_xg0[(size_t)row * NGATE + col]       = c[0] + bias0;
                g_xg0[(size_t)(row + 8) * NGATE + col] = c[2] + bias0;
            }
            if (col + 1 < NGATE) {
                g_xg0[(size_t)row * NGATE + col + 1]       = c[1] + bias1;
                g_xg0[(size_t)(row + 8) * NGATE + col + 1] = c[3] + bias1;
            }
        }
    }
}

// ---------------------------------------------------------------------------
// Kernel 2: fused 2-layer recurrent LSTM + final linear.
// ONE barrier per phase. Gate quad (i,f,g,o of hidden unit j) lives in one
// lane-quad: lane = 4*u + q, unit j = warp*8 + u, gate row = q*30 + j.
// Warps 0-3: layer0 (t=p). Warps 4-7: layer1 (t=p-1). Hidden states are
// double-buffered float4 (NB=4 batches packed); SHFL combines the quad and
// lane q==0 performs the c/h update + h store.
// ---------------------------------------------------------------------------
__device__ __forceinline__ float sig_raw(float x) {
    return __fdividef(1.0f, 1.0f + __expf(-x));
}
__device__ __forceinline__ float tanh_f(float x) {
    return fmaf(2.0f, sig_raw(2.0f * x), -1.0f);
}

__global__ __launch_bounds__(256, 2) void lstm_rec(
    const float* __restrict__ w_hh0,  // [120,30]
    const float* __restrict__ w_ih1,  // [120,30]
    const float* __restrict__ w_hh1,  // [120,30]
    const float* __restrict__ b_ih1,  // [120]
    const float* __restrict__ b_hh1,  // [120]
    const float* __restrict__ w_lin,  // [3840] (t*30+j)
    const float* __restrict__ b_lin,  // [1]
    float* __restrict__ out)          // [1024]
{
    const int b0   = blockIdx.x * NB;
    const int tid  = threadIdx.x;
    const int wid  = tid >> 5;
    const int lane = tid & 31;
    const int layer = wid >> 2;            // 0: warps 0-3, 1: warps 4-7
    const int wi    = wid & 3;
    const int j     = wi * 8 + (lane >> 2); // 0..31 (30,31 dummy)
    const int q     = lane & 3;             // gate: 0=i,1=f,2=g,3=o
    const bool jok  = (j < NHID);
    const int jc    = jok ? j : (NHID - 1);
    const int gr    = q * 30 + jc;          // gate row index

    __shared__ float4 sh_h0[2][NHID];
    __shared__ float4 sh_h1[2][NHID];
    __shared__ float  sh_red[NB][32];

    // Per-thread weight rows
    float wK0[NHID], wK1[NHID];
    float bias1 = 0.0f;
    if (layer == 0) {
#pragma unroll
        for (int k = 0; k < NHID; k++) wK0[k] = w_hh0[gr * NHID + k];
    } else {
#pragma unroll
        for (int k = 0; k < NHID; k++) {
            wK0[k] = w_ih1[gr * NHID + k];
            wK1[k] = w_hh1[gr * NHID + k];
        }
        bias1 = b_ih1[gr] + b_hh1[gr];
    }

    float c[NB], outacc[NB];
#pragma unroll
    for (int bb = 0; bb < NB; bb++) { c[bb] = 0.0f; outacc[bb] = 0.0f; }

    if (tid < NHID) {
        float4 z = make_float4(0.f, 0.f, 0.f, 0.f);
        sh_h0[0][tid] = z; sh_h0[1][tid] = z;
        sh_h1[0][tid] = z; sh_h1[1][tid] = z;
    }

    // xg prefetch (layer0 only)
    float xg_cur[NB];
    if (layer == 0) {
#pragma unroll
        for (int bb = 0; bb < NB; bb++)
            xg_cur[bb] = __ldg(&g_xg0[((size_t)(b0 + bb) * SEQLEN) * NGATE + gr]);
    }
    __syncthreads();

    // Branchless activation constants: q==2 -> tanh = 2*sig(2x)-1
    const float a_scale = (q == 2) ? 2.0f : 1.0f;
    const float a_mult  = (q == 2) ? 2.0f : 1.0f;
    const float a_add   = (q == 2) ? -1.0f : 0.0f;

    for (int p = 0; p <= SEQLEN; p++) {
        const int wb = p & 1;
        const int rb = wb ^ 1;
        float val[NB];
        bool active;

        if (layer == 0) {
            active = (p < SEQLEN);
            if (active) {
                float a0 = xg_cur[0], a1 = xg_cur[1], a2 = xg_cur[2], a3 = xg_cur[3];
                if (p + 1 < SEQLEN) {
#pragma unroll
                    for (int bb = 0; bb < NB; bb++)
                        xg_cur[bb] = __ldg(&g_xg0[((size_t)(b0 + bb) * SEQLEN + p + 1) * NGATE + gr]);
                }
#pragma unroll
                for (int k = 0; k < NHID; k++) {
                    float4 h = sh_h0[rb][k];
                    float  w = wK0[k];
                    a0 = fmaf(h.x, w, a0);
                    a1 = fmaf(h.y, w, a1);
                    a2 = fmaf(h.z, w, a2);
                    a3 = fmaf(h.w, w, a3);
                }
                val[0] = fmaf(a_mult, sig_raw(a0 * a_scale), a_add);
                val[1] = fmaf(a_mult, sig_raw(a1 * a_scale), a_add);
                val[2] = fmaf(a_mult, sig_raw(a2 * a_scale), a_add);
                val[3] = fmaf(a_mult, sig_raw(a3 * a_scale), a_add);
            }
        } else {
            active = (p >= 1);
            if (active) {
                float aA0 = bias1, aA1 = bias1, aA2 = bias1, aA3 = bias1;
                float aB0 = 0.f, aB1 = 0.f, aB2 = 0.f, aB3 = 0.f;
#pragma unroll
                for (int k = 0; k < NHID; k++) {
                    float4 h0 = sh_h0[rb][k];
                    float4 h1 = sh_h1[rb][k];
                    float  wa = wK0[k], wb2 = wK1[k];
                    aA0 = fmaf(h0.x, wa, aA0);
                    aA1 = fmaf(h0.y, wa, aA1);
                    aA2 = fmaf(h0.z, wa, aA2);
                    aA3 = fmaf(h0.w, wa, aA3);
                    aB0 = fmaf(h1.x, wb2, aB0);
                    aB1 = fmaf(h1.y, wb2, aB1);
                    aB2 = fmaf(h1.z, wb2, aB2);
                    aB3 = fmaf(h1.w, wb2, aB3);
                }
                val[0] = fmaf(a_mult, sig_raw((aA0 + aB0) * a_scale), a_add);
                val[1] = fmaf(a_mult, sig_raw((aA1 + aB1) * a_scale), a_add);
                val[2] = fmaf(a_mult, sig_raw((aA2 + aB2) * a_scale), a_add);
                val[3] = fmaf(a_mult, sig_raw((aA3 + aB3) * a_scale), a_add);
            }
        }

        if (active) {
            const int base = lane & ~3;
            float iv[NB], fv[NB], gv[NB], ov[NB];
#pragma unroll
            for (int bb = 0; bb < NB; bb++) {
                iv[bb] = __shfl_sync(0xffffffffu, val[bb], base + 0);
                fv[bb] = __shfl_sync(0xffffffffu, val[bb], base + 1);
                gv[bb] = __shfl_sync(0xffffffffu, val[bb], base + 2);
                ov[bb] = __shfl_sync(0xffffffffu, val[bb], base + 3);
            }
            if (q == 0 && jok) {
                float4 hv;
                float* hp = (float*)&hv;
                float wl = 0.0f;
                if (layer == 1) wl = __ldg(&w_lin[(p - 1) * NHID + j]);
#pragma unroll
                for (int bb = 0; bb < NB; bb++) {
                    c[bb] = fmaf(fv[bb], c[bb], iv[bb] * gv[bb]);
                    float h = ov[bb] * tanh_f(c[bb]);
                    hp[bb] = h;
                    if (layer == 1) outacc[bb] = fmaf(h, wl, outacc[bb]);
                }
                if (layer == 0) sh_h0[wb][j] = hv;
                else            sh_h1[wb][j] = hv;
            }
        }
        __syncthreads();
    }

    // Output reduction: layer1 q0 lanes hold outacc[bb] per unit j
    if (layer == 1 && q == 0 && jok) {
#pragma unroll
        for (int bb = 0; bb < NB; bb++) sh_red[bb][j] = outacc[bb];
    }
    __syncthreads();
    if (tid < NB) {
        float s = b_lin[0];
#pragma unroll
        for (int jj = 0; jj < NHID; jj++) s += sh_red[tid][jj];
        out[b0 + tid] = s;
    }
}

// ---------------------------------------------------------------------------
// Entry point
// ---------------------------------------------------------------------------
extern "C" void kernel_launch(void* const* d_in, const int* in_sizes, int n_in,
                              void* d_out, int out_size)
{
    const float* x      = (const float*)d_in[0];
    const float* w_ih0  = (const float*)d_in[1];
    const float* w_hh0  = (const float*)d_in[2];
    const float* b_ih0  = (const float*)d_in[3];
    const float* b_hh0  = (const float*)d_in[4];
    const float* w_ih1  = (const float*)d_in[5];
    const float* w_hh1  = (const float*)d_in[6];
    const float* b_ih1  = (const float*)d_in[7];
    const float* b_hh1  = (const float*)d_in[8];
    const float* w_lin  = (const float*)d_in[9];
    const float* b_lin  = (const float*)d_in[10];
    float* out = (float*)d_out;

    gemm_xg0_tc<<<MROWS / 128, 256>>>(x, w_ih0, b_ih0, b_hh0);
    lstm_rec<<<BATCH / NB, 256>>>(w_hh0, w_ih1, w_hh1, b_ih1, b_hh1, w_lin, b_lin, out);
}

// round 7
// speedup vs baseline: 2.0556x; 1.1403x over previous
#include <cuda_runtime.h>
#include <cuda_bf16.h>
#include <cstdint>

// Problem constants
#define BATCH   1024
#define SEQLEN  128
#define NFEAT   256
#define NHID    30
#define NGATE   120          // 4*NHID
#define MROWS   (BATCH*SEQLEN)   // 131072
#define NB      4            // batch elements per recurrent CTA

__device__ float g_xg0[(size_t)MROWS * NGATE];

// ---------------------------------------------------------------------------
// packed f32x2 helpers (sm_103a FFMA2 — only reachable via PTX)
// ---------------------------------------------------------------------------
__device__ __forceinline__ void ffma2(uint64_t& d, uint64_t a, uint64_t b) {
    asm("fma.rn.f32x2 %0, %1, %2, %0;" : "+l"(d) : "l"(a), "l"(b));
}
__device__ __forceinline__ uint64_t pack2(float lo, float hi) {
    uint64_t r;
    asm("mov.b64 %0, {%1,%2};" : "=l"(r) : "f"(lo), "f"(hi));
    return r;
}
__device__ __forceinline__ float2 unpack2(uint64_t v) {
    float2 r;
    asm("mov.b64 {%0,%1}, %2;" : "=f"(r.x), "=f"(r.y) : "l"(v));
    return r;
}

// ---------------------------------------------------------------------------
// Kernel 1: xg0 = x @ w_ih0^T + (b_ih0 + b_hh0)   -- tensor-core split-bf16
// ---------------------------------------------------------------------------
#define BK     32
#define SAS    40

__device__ __forceinline__ uint32_t smem_u32(const void* p) {
    return (uint32_t)__cvta_generic_to_shared(p);
}
__device__ __forceinline__ void ldm_x4(uint32_t addr, uint32_t& r0, uint32_t& r1,
                                       uint32_t& r2, uint32_t& r3) {
    asm volatile("ldmatrix.sync.aligned.m8n8.x4.shared.b16 {%0,%1,%2,%3}, [%4];"
                 : "=r"(r0), "=r"(r1), "=r"(r2), "=r"(r3) : "r"(addr));
}
__device__ __forceinline__ void ldm_x2(uint32_t addr, uint32_t& r0, uint32_t& r1) {
    asm volatile("ldmatrix.sync.aligned.m8n8.x2.shared.b16 {%0,%1}, [%2];"
                 : "=r"(r0), "=r"(r1) : "r"(addr));
}
__device__ __forceinline__ void mma_bf16(float* c, const uint32_t* a, const uint32_t* b) {
    asm volatile(
        "mma.sync.aligned.m16n8k16.row.col.f32.bf16.bf16.f32 "
        "{%0,%1,%2,%3}, {%4,%5,%6,%7}, {%8,%9}, {%0,%1,%2,%3};"
        : "+f"(c[0]), "+f"(c[1]), "+f"(c[2]), "+f"(c[3])
        : "r"(a[0]), "r"(a[1]), "r"(a[2]), "r"(a[3]), "r"(b[0]), "r"(b[1]));
}
__device__ __forceinline__ void cvt_hilo(float4 v, uint2& hi, uint2& lo) {
    uint32_t bx = __float_as_uint(v.x), by = __float_as_uint(v.y);
    uint32_t bz = __float_as_uint(v.z), bw = __float_as_uint(v.w);
    hi.x = __byte_perm(bx, by, 0x7632);
    hi.y = __byte_perm(bz, bw, 0x7632);
    float lx = v.x - __uint_as_float(bx & 0xffff0000u);
    float ly = v.y - __uint_as_float(by & 0xffff0000u);
    float lz = v.z - __uint_as_float(bz & 0xffff0000u);
    float lw = v.w - __uint_as_float(bw & 0xffff0000u);
    __nv_bfloat162 l01 = __floats2bfloat162_rn(lx, ly);
    __nv_bfloat162 l23 = __floats2bfloat162_rn(lz, lw);
    lo.x = *reinterpret_cast<uint32_t*>(&l01);
    lo.y = *reinterpret_cast<uint32_t*>(&l23);
}

__global__ __launch_bounds__(256) void gemm_xg0_tc(
    const float* __restrict__ x,
    const float* __restrict__ w,
    const float* __restrict__ b_ih,
    const float* __restrict__ b_hh)
{
    __shared__ __nv_bfloat16 sAhi[128 * SAS];
    __shared__ __nv_bfloat16 sAlo[128 * SAS];
    __shared__ __nv_bfloat16 sBhi[128 * SAS];
    __shared__ __nv_bfloat16 sBlo[128 * SAS];

    const int tid  = threadIdx.x;
    const int lane = tid & 31;
    const int wid  = tid >> 5;
    const int m0   = blockIdx.x * 128;

    const int wm = wid & 1;
    const int wn = wid >> 1;
    const int warp_m = wm * 64;
    const int warp_n = wn * 32;

    float acc[4][4][4];
#pragma unroll
    for (int i = 0; i < 4; i++)
#pragma unroll
        for (int j = 0; j < 4; j++)
#pragma unroll
            for (int k = 0; k < 4; k++) acc[i][j][k] = 0.0f;

    const int a_mo = (lane & 7) + ((lane >> 3) & 1) * 8;
    const int a_ko = ((lane >> 4) & 1) * 8;
    const int bl   = lane & 15;
    const int b_no = bl & 7;
    const int b_ko = ((bl >> 3) & 1) * 8;

    for (int k0 = 0; k0 < NFEAT; k0 += BK) {
#pragma unroll
        for (int i = 0; i < 4; i++) {
            int idx = tid + i * 256;
            int row = idx >> 3;
            int c4  = idx & 7;
            float4 v = *reinterpret_cast<const float4*>(
                x + (size_t)(m0 + row) * NFEAT + k0 + c4 * 4);
            uint2 hi, lo;
            cvt_hilo(v, hi, lo);
            *reinterpret_cast<uint2*>(&sAhi[row * SAS + c4 * 4]) = hi;
            *reinterpret_cast<uint2*>(&sAlo[row * SAS + c4 * 4]) = lo;
        }
#pragma unroll
        for (int i = 0; i < 4; i++) {
            int idx = tid + i * 256;
            int n   = idx >> 3;
            int c4  = idx & 7;
            float4 v = make_float4(0.f, 0.f, 0.f, 0.f);
            if (n < NGATE)
                v = *reinterpret_cast<const float4*>(
                    w + (size_t)n * NFEAT + k0 + c4 * 4);
            uint2 hi, lo;
            cvt_hilo(v, hi, lo);
            *reinterpret_cast<uint2*>(&sBhi[n * SAS + c4 * 4]) = hi;
            *reinterpret_cast<uint2*>(&sBlo[n * SAS + c4 * 4]) = lo;
        }
        __syncthreads();

#pragma unroll
        for (int ks = 0; ks < BK; ks += 16) {
            uint32_t ahi[4][4], alo[4][4], bhi[4][2], blo[4][2];
#pragma unroll
            for (int mi = 0; mi < 4; mi++) {
                int mrow = warp_m + mi * 16 + a_mo;
                int kcol = ks + a_ko;
                ldm_x4(smem_u32(&sAhi[mrow * SAS + kcol]),
                       ahi[mi][0], ahi[mi][1], ahi[mi][2], ahi[mi][3]);
                ldm_x4(smem_u32(&sAlo[mrow * SAS + kcol]),
                       alo[mi][0], alo[mi][1], alo[mi][2], alo[mi][3]);
            }
#pragma unroll
            for (int ni = 0; ni < 4; ni++) {
                int nrow = warp_n + ni * 8 + b_no;
                int kcol = ks + b_ko;
                ldm_x2(smem_u32(&sBhi[nrow * SAS + kcol]), bhi[ni][0], bhi[ni][1]);
                ldm_x2(smem_u32(&sBlo[nrow * SAS + kcol]), blo[ni][0], blo[ni][1]);
            }
#pragma unroll
            for (int mi = 0; mi < 4; mi++)
#pragma unroll
                for (int ni = 0; ni < 4; ni++) {
                    mma_bf16(acc[mi][ni], ahi[mi], bhi[ni]);
                    mma_bf16(acc[mi][ni], ahi[mi], blo[ni]);
                    mma_bf16(acc[mi][ni], alo[mi], bhi[ni]);
                }
        }
        __syncthreads();
    }

    // epilogue: paired STG.64 (col, col+1), col even
    const int gid  = lane >> 2;
    const int tig  = lane & 3;
#pragma unroll
    for (int ni = 0; ni < 4; ni++) {
        int col = warp_n + ni * 8 + tig * 2;
        if (col < NGATE) {
            float bx = b_ih[col] + b_hh[col];
            float by = b_ih[col + 1] + b_hh[col + 1];
#pragma unroll
            for (int mi = 0; mi < 4; mi++) {
                int row = m0 + warp_m + mi * 16 + gid;
                float* c = acc[mi][ni];
                *reinterpret_cast<float2*>(&g_xg0[(size_t)row * NGATE + col]) =
                    make_float2(c[0] + bx, c[1] + by);
                *reinterpret_cast<float2*>(&g_xg0[(size_t)(row + 8) * NGATE + col]) =
                    make_float2(c[2] + bx, c[3] + by);
            }
        }
    }
}

// ---------------------------------------------------------------------------
// Kernel 2: fused 2-layer recurrent LSTM + final linear — FFMA2 edition.
// Warps 0-3: layer0 (t=p); warps 4-7: layer1 (t=p-1); one barrier per phase.
// Lane quad (q=0..3) owns the 4 gate rows of hidden unit j; after the dot,
// a 4x4 shfl transpose hands lane q the (i,f,g,o) of batch q, so the c/h
// update runs on all 4 lanes in parallel.
// Layer0: wp[k]={w,w}, acc packed over batch pairs -> 60 FFMA2.
// Layer1: wp[k]={wA,wB}, h stored interleaved {h0,h1} per batch -> 120 FFMA2.
// ---------------------------------------------------------------------------
__device__ __forceinline__ float sig_raw(float x) {
    return __fdividef(1.0f, 1.0f + __expf(-x));
}
__device__ __forceinline__ float tanh_f(float x) {
    return fmaf(2.0f, sig_raw(2.0f * x), -1.0f);
}

__global__ __launch_bounds__(256, 2) void lstm_rec(
    const float* __restrict__ w_hh0,
    const float* __restrict__ w_ih1,
    const float* __restrict__ w_hh1,
    const float* __restrict__ b_ih1,
    const float* __restrict__ b_hh1,
    const float* __restrict__ w_lin,
    const float* __restrict__ b_lin,
    float* __restrict__ out)
{
    const int b0   = blockIdx.x * NB;
    const int tid  = threadIdx.x;
    const int wid  = tid >> 5;
    const int lane = tid & 31;
    const int layer = wid >> 2;
    const int wi    = wid & 3;
    const int j     = wi * 8 + (lane >> 2);
    const int q     = lane & 3;
    const bool jok  = (j < NHID);
    const int jc    = jok ? j : (NHID - 1);
    const int gr    = q * 30 + jc;

    // h0 packed by batch (for layer0 reads); {h0,h1} interleaved per batch
    // (for layer1 reads): hA = batches 0,1 ; hB = batches 2,3.
    __shared__ float4 sh_h0p[2][NHID];
    __shared__ float4 sh_hA[2][NHID];
    __shared__ float4 sh_hB[2][NHID];
    __shared__ float  sh_red[NB][32];

    // Unified packed weights: layer0 {w,w}; layer1 {wA,wB}
    uint64_t wp[NHID];
    float bias1 = 0.0f;
    if (layer == 0) {
#pragma unroll
        for (int k = 0; k < NHID; k++) {
            float w = w_hh0[gr * NHID + k];
            wp[k] = pack2(w, w);
        }
    } else {
#pragma unroll
        for (int k = 0; k < NHID; k++)
            wp[k] = pack2(w_ih1[gr * NHID + k], w_hh1[gr * NHID + k]);
        bias1 = b_ih1[gr] + b_hh1[gr];
    }

    float c = 0.0f, outacc = 0.0f;

    if (tid < NHID) {
        float4 z = make_float4(0.f, 0.f, 0.f, 0.f);
        sh_h0p[0][tid] = z; sh_h0p[1][tid] = z;
        sh_hA[0][tid]  = z; sh_hA[1][tid]  = z;
        sh_hB[0][tid]  = z; sh_hB[1][tid]  = z;
    }

    float xg_cur[NB];
    if (layer == 0) {
#pragma unroll
        for (int bb = 0; bb < NB; bb++)
            xg_cur[bb] = __ldg(&g_xg0[((size_t)(b0 + bb) * SEQLEN) * NGATE + gr]);
    }
    __syncthreads();

    // Branchless activation constants: q==2 (g gate) -> tanh = 2*sig(2x)-1
    const float a_scale = (q == 2) ? 2.0f : 1.0f;
    const float a_mult  = (q == 2) ? 2.0f : 1.0f;
    const float a_add   = (q == 2) ? -1.0f : 0.0f;

    for (int p = 0; p <= SEQLEN; p++) {
        const int wb = p & 1;
        const int rb = wb ^ 1;
        const bool active = (layer == 0) ? (p < SEQLEN) : (p >= 1);

        if (active) {
            float v0, v1, v2, v3;
            float wl = 0.0f;
            if (layer == 0) {
                uint64_t a01 = pack2(xg_cur[0], xg_cur[1]);
                uint64_t a23 = pack2(xg_cur[2], xg_cur[3]);
                if (p + 1 < SEQLEN) {
#pragma unroll
                    for (int bb = 0; bb < NB; bb++)
                        xg_cur[bb] = __ldg(&g_xg0[((size_t)(b0 + bb) * SEQLEN + p + 1) * NGATE + gr]);
                }
#pragma unroll
                for (int k = 0; k < NHID; k++) {
                    ulonglong2 h = *reinterpret_cast<const ulonglong2*>(&sh_h0p[rb][k]);
                    ffma2(a01, wp[k], h.x);
                    ffma2(a23, wp[k], h.y);
                }
                float2 p01 = unpack2(a01), p23 = unpack2(a23);
                v0 = p01.x; v1 = p01.y; v2 = p23.x; v3 = p23.y;
            } else {
                uint64_t a0 = pack2(bias1, 0.f);
                uint64_t a1 = a0, a2 = a0, a3 = a0;
                wl = __ldg(&w_lin[(p - 1) * NHID + jc]);
#pragma unroll
                for (int k = 0; k < NHID; k++) {
                    ulonglong2 hA = *reinterpret_cast<const ulonglong2*>(&sh_hA[rb][k]);
                    ulonglong2 hB = *reinterpret_cast<const ulonglong2*>(&sh_hB[rb][k]);
                    ffma2(a0, wp[k], hA.x);
                    ffma2(a1, wp[k], hA.y);
                    ffma2(a2, wp[k], hB.x);
                    ffma2(a3, wp[k], hB.y);
                }
                float2 r0 = unpack2(a0), r1 = unpack2(a1);
                float2 r2 = unpack2(a2), r3 = unpack2(a3);
                v0 = r0.x + r0.y; v1 = r1.x + r1.y;
                v2 = r2.x + r2.y; v3 = r3.x + r3.y;
            }
            // activation (lane's own gate type for all 4 batches)
            v0 = fmaf(a_mult, sig_raw(v0 * a_scale), a_add);
            v1 = fmaf(a_mult, sig_raw(v1 * a_scale), a_add);
            v2 = fmaf(a_mult, sig_raw(v2 * a_scale), a_add);
            v3 = fmaf(a_mult, sig_raw(v3 * a_scale), a_add);

            // 4x4 quad transpose: lane q ends with (i,f,g,o) of batch q
            float s1 = (q & 1) ? v0 : v1;
            float r1s = __shfl_xor_sync(0xffffffffu, s1, 1);
            float s2 = (q & 1) ? v2 : v3;
            float r2s = __shfl_xor_sync(0xffffffffu, s2, 1);
            float u0 = (q & 1) ? r1s : v0;
            float u1 = (q & 1) ? v1 : r1s;
            float u2 = (q & 1) ? r2s : v2;
            float u3 = (q & 1) ? v3 : r2s;
            float s3 = (q & 2) ? u0 : u2;
            float r3s = __shfl_xor_sync(0xffffffffu, s3, 2);
            float s4 = (q & 2) ? u1 : u3;
            float r4s = __shfl_xor_sync(0xffffffffu, s4, 2);
            float ti = (q & 2) ? r3s : u0;
            float tf = (q & 2) ? r4s : u1;
            float tg = (q & 2) ? u2 : r3s;
            float to = (q & 2) ? u3 : r4s;

            // per-lane update: lane q = batch q
            c = fmaf(tf, c, ti * tg);
            float h = to * tanh_f(c);
            if (jok) {
                float* pb = (q < 2) ? (float*)&sh_hA[wb][j] : (float*)&sh_hB[wb][j];
                pb[(q & 1) * 2 + layer] = h;
                if (layer == 0) {
                    ((float*)&sh_h0p[wb][j])[q] = h;
                } else {
                    outacc = fmaf(h, wl, outacc);
                }
            }
        }
        __syncthreads();
    }

    // output reduction: layer1 lane (q, j) holds partial for batch q
    if (layer == 1 && jok) sh_red[q][j] = outacc;
    __syncthreads();
    if (tid < NB) {
        float s = b_lin[0];
#pragma unroll
        for (int jj = 0; jj < NHID; jj++) s += sh_red[tid][jj];
        out[b0 + tid] = s;
    }
}

// ---------------------------------------------------------------------------
// Entry point
// ---------------------------------------------------------------------------
extern "C" void kernel_launch(void* const* d_in, const int* in_sizes, int n_in,
                              void* d_out, int out_size)
{
    const float* x      = (const float*)d_in[0];
    const float* w_ih0  = (const float*)d_in[1];
    const float* w_hh0  = (const float*)d_in[2];
    const float* b_ih0  = (const float*)d_in[3];
    const float* b_hh0  = (const float*)d_in[4];
    const float* w_ih1  = (const float*)d_in[5];
    const float* w_hh1  = (const float*)d_in[6];
    const float* b_ih1  = (const float*)d_in[7];
    const float* b_hh1  = (const float*)d_in[8];
    const float* w_lin  = (const float*)d_in[9];
    const float* b_lin  = (const float*)d_in[10];
    float* out = (float*)d_out;

    gemm_xg0_tc<<<MROWS / 128, 256>>>(x, w_ih0, b_ih0, b_hh0);
    lstm_rec<<<BATCH / NB, 256>>>(w_hh0, w_ih1, w_hh1, b_ih1, b_hh1, w_lin, b_lin, out);
}

// round 8
// speedup vs baseline: 2.1362x; 1.0392x over previous
#include <cuda_runtime.h>
#include <cuda_bf16.h>
#include <cstdint>

// Problem constants
#define BATCH   1024
#define SEQLEN  128
#define NFEAT   256
#define NHID    30
#define NGATE   120          // 4*NHID
#define MROWS   (BATCH*SEQLEN)   // 131072
#define NB      4            // batch elements per recurrent CTA

__device__ float g_xg0[(size_t)MROWS * NGATE];
// Pre-converted w_ih0 (split bf16, zero-padded to 128 rows)
__device__ __nv_bfloat16 g_whi[128 * NFEAT];
__device__ __nv_bfloat16 g_wlo[128 * NFEAT];

// ---------------------------------------------------------------------------
// packed f32x2 helpers (sm_103a FFMA2 — only reachable via PTX)
// ---------------------------------------------------------------------------
__device__ __forceinline__ void ffma2(uint64_t& d, uint64_t a, uint64_t b) {
    asm("fma.rn.f32x2 %0, %1, %2, %0;" : "+l"(d) : "l"(a), "l"(b));
}
__device__ __forceinline__ uint64_t pack2(float lo, float hi) {
    uint64_t r;
    asm("mov.b64 %0, {%1,%2};" : "=l"(r) : "f"(lo), "f"(hi));
    return r;
}
__device__ __forceinline__ float2 unpack2(uint64_t v) {
    float2 r;
    asm("mov.b64 {%0,%1}, %2;" : "=f"(r.x), "=f"(r.y) : "l"(v));
    return r;
}

// ---------------------------------------------------------------------------
// Kernel 0: one-shot conversion of w_ih0 -> split bf16 (hi = trunc, lo = resid)
// ---------------------------------------------------------------------------
__global__ __launch_bounds__(256) void wcvt(const float* __restrict__ w) {
    int t = blockIdx.x * 256 + threadIdx.x;    // 0 .. 32767
    int n = t >> 8;                            // 0..127
    float v = 0.0f;
    if (n < NGATE) v = w[t - (n << 8) + n * NFEAT];  // w[n*256 + k]
    uint32_t b = __float_as_uint(v);
    unsigned short hs = (unsigned short)(b >> 16);
    float lo = v - __uint_as_float(b & 0xffff0000u);
    *reinterpret_cast<unsigned short*>(&g_whi[t]) = hs;
    g_wlo[t] = __float2bfloat16(lo);
}

// ---------------------------------------------------------------------------
// Kernel 1: xg0 = x @ w_ih0^T + (b_ih0 + b_hh0)   -- tensor-core split-bf16
// Register-prefetch pipelined over 8 K-chunks; B pre-converted in gmem.
// ---------------------------------------------------------------------------
#define BK     32
#define SAS    40

__device__ __forceinline__ uint32_t smem_u32(const void* p) {
    return (uint32_t)__cvta_generic_to_shared(p);
}
__device__ __forceinline__ void ldm_x4(uint32_t addr, uint32_t& r0, uint32_t& r1,
                                       uint32_t& r2, uint32_t& r3) {
    asm volatile("ldmatrix.sync.aligned.m8n8.x4.shared.b16 {%0,%1,%2,%3}, [%4];"
                 : "=r"(r0), "=r"(r1), "=r"(r2), "=r"(r3) : "r"(addr));
}
__device__ __forceinline__ void ldm_x2(uint32_t addr, uint32_t& r0, uint32_t& r1) {
    asm volatile("ldmatrix.sync.aligned.m8n8.x2.shared.b16 {%0,%1}, [%2];"
                 : "=r"(r0), "=r"(r1) : "r"(addr));
}
__device__ __forceinline__ void mma_bf16(float* c, const uint32_t* a, const uint32_t* b) {
    asm volatile(
        "mma.sync.aligned.m16n8k16.row.col.f32.bf16.bf16.f32 "
        "{%0,%1,%2,%3}, {%4,%5,%6,%7}, {%8,%9}, {%0,%1,%2,%3};"
        : "+f"(c[0]), "+f"(c[1]), "+f"(c[2]), "+f"(c[3])
        : "r"(a[0]), "r"(a[1]), "r"(a[2]), "r"(a[3]), "r"(b[0]), "r"(b[1]));
}
__device__ __forceinline__ void cvt_hilo(float4 v, uint2& hi, uint2& lo) {
    uint32_t bx = __float_as_uint(v.x), by = __float_as_uint(v.y);
    uint32_t bz = __float_as_uint(v.z), bw = __float_as_uint(v.w);
    hi.x = __byte_perm(bx, by, 0x7632);
    hi.y = __byte_perm(bz, bw, 0x7632);
    float lx = v.x - __uint_as_float(bx & 0xffff0000u);
    float ly = v.y - __uint_as_float(by & 0xffff0000u);
    float lz = v.z - __uint_as_float(bz & 0xffff0000u);
    float lw = v.w - __uint_as_float(bw & 0xffff0000u);
    __nv_bfloat162 l01 = __floats2bfloat162_rn(lx, ly);
    __nv_bfloat162 l23 = __floats2bfloat162_rn(lz, lw);
    lo.x = *reinterpret_cast<uint32_t*>(&l01);
    lo.y = *reinterpret_cast<uint32_t*>(&l23);
}

__global__ __launch_bounds__(256, 2) void gemm_xg0_tc(
    const float* __restrict__ x,
    const float* __restrict__ b_ih,
    const float* __restrict__ b_hh)
{
    __shared__ __nv_bfloat16 sAhi[128 * SAS];
    __shared__ __nv_bfloat16 sAlo[128 * SAS];
    __shared__ __nv_bfloat16 sBhi[128 * SAS];
    __shared__ __nv_bfloat16 sBlo[128 * SAS];

    const int tid  = threadIdx.x;
    const int lane = tid & 31;
    const int wid  = tid >> 5;
    const int m0   = blockIdx.x * 128;

    const int wm = wid & 1;
    const int wn = wid >> 1;
    const int warp_m = wm * 64;
    const int warp_n = wn * 32;

    float acc[4][4][4];
#pragma unroll
    for (int i = 0; i < 4; i++)
#pragma unroll
        for (int j = 0; j < 4; j++)
#pragma unroll
            for (int k = 0; k < 4; k++) acc[i][j][k] = 0.0f;

    const int a_mo = (lane & 7) + ((lane >> 3) & 1) * 8;
    const int a_ko = ((lane >> 4) & 1) * 8;
    const int bl   = lane & 15;
    const int b_no = bl & 7;
    const int b_ko = ((bl >> 3) & 1) * 8;

    // B loader mapping: thread t handles row n = t&127 of array sel = t>>7
    const int  b_row = tid & 127;
    const bool b_lo  = (tid >> 7) & 1;
    const __nv_bfloat16* bsrc = b_lo ? g_wlo : g_whi;
    __nv_bfloat16*       bdst = b_lo ? sBlo  : sBhi;

    // ---- prologue: prefetch chunk 0 into registers
    float4 ra[4];
    uint4  rb[4];
#pragma unroll
    for (int i = 0; i < 4; i++) {
        int idx = tid + i * 256;
        int row = idx >> 3;
        int c4  = idx & 7;
        ra[i] = *reinterpret_cast<const float4*>(
            x + (size_t)(m0 + row) * NFEAT + c4 * 4);
    }
#pragma unroll
    for (int i = 0; i < 4; i++)
        rb[i] = *reinterpret_cast<const uint4*>(bsrc + b_row * NFEAT + i * 8);

    for (int k0 = 0; k0 < NFEAT; k0 += BK) {
        // ---- store prefetched chunk to smem (A converts, B is raw bf16)
#pragma unroll
        for (int i = 0; i < 4; i++) {
            int idx = tid + i * 256;
            int row = idx >> 3;
            int c4  = idx & 7;
            uint2 hi, lo;
            cvt_hilo(ra[i], hi, lo);
            *reinterpret_cast<uint2*>(&sAhi[row * SAS + c4 * 4]) = hi;
            *reinterpret_cast<uint2*>(&sAlo[row * SAS + c4 * 4]) = lo;
        }
#pragma unroll
        for (int i = 0; i < 4; i++)
            *reinterpret_cast<uint4*>(&bdst[b_row * SAS + i * 8]) = rb[i];
        __syncthreads();

        // ---- prefetch next chunk (LDG latency hides under mma below)
        if (k0 + BK < NFEAT) {
#pragma unroll
            for (int i = 0; i < 4; i++) {
                int idx = tid + i * 256;
                int row = idx >> 3;
                int c4  = idx & 7;
                ra[i] = *reinterpret_cast<const float4*>(
                    x + (size_t)(m0 + row) * NFEAT + (k0 + BK) + c4 * 4);
            }
#pragma unroll
            for (int i = 0; i < 4; i++)
                rb[i] = *reinterpret_cast<const uint4*>(
                    bsrc + b_row * NFEAT + (k0 + BK) + i * 8);
        }

        // ---- mma over the smem tile
#pragma unroll
        for (int ks = 0; ks < BK; ks += 16) {
            uint32_t ahi[4][4], alo[4][4], bhi[4][2], blo[4][2];
#pragma unroll
            for (int mi = 0; mi < 4; mi++) {
                int mrow = warp_m + mi * 16 + a_mo;
                int kcol = ks + a_ko;
                ldm_x4(smem_u32(&sAhi[mrow * SAS + kcol]),
                       ahi[mi][0], ahi[mi][1], ahi[mi][2], ahi[mi][3]);
                ldm_x4(smem_u32(&sAlo[mrow * SAS + kcol]),
                       alo[mi][0], alo[mi][1], alo[mi][2], alo[mi][3]);
            }
#pragma unroll
            for (int ni = 0; ni < 4; ni++) {
                int nrow = warp_n + ni * 8 + b_no;
                int kcol = ks + b_ko;
                ldm_x2(smem_u32(&sBhi[nrow * SAS + kcol]), bhi[ni][0], bhi[ni][1]);
                ldm_x2(smem_u32(&sBlo[nrow * SAS + kcol]), blo[ni][0], blo[ni][1]);
            }
#pragma unroll
            for (int mi = 0; mi < 4; mi++)
#pragma unroll
                for (int ni = 0; ni < 4; ni++) {
                    mma_bf16(acc[mi][ni], ahi[mi], bhi[ni]);
                    mma_bf16(acc[mi][ni], ahi[mi], blo[ni]);
                    mma_bf16(acc[mi][ni], alo[mi], bhi[ni]);
                }
        }
        __syncthreads();
    }

    // epilogue: paired STG.64 (col, col+1), col even
    const int gid  = lane >> 2;
    const int tig  = lane & 3;
#pragma unroll
    for (int ni = 0; ni < 4; ni++) {
        int col = warp_n + ni * 8 + tig * 2;
        if (col < NGATE) {
            float bx = b_ih[col] + b_hh[col];
            float by = b_ih[col + 1] + b_hh[col + 1];
#pragma unroll
            for (int mi = 0; mi < 4; mi++) {
                int row = m0 + warp_m + mi * 16 + gid;
                float* c = acc[mi][ni];
                *reinterpret_cast<float2*>(&g_xg0[(size_t)row * NGATE + col]) =
                    make_float2(c[0] + bx, c[1] + by);
                *reinterpret_cast<float2*>(&g_xg0[(size_t)(row + 8) * NGATE + col]) =
                    make_float2(c[2] + bx, c[3] + by);
            }
        }
    }
}

// ---------------------------------------------------------------------------
// Kernel 2: fused 2-layer recurrent LSTM + final linear — FFMA2 edition.
// (unchanged from round 7: 140us, within ~1.4x of its fma-pipe floor)
// ---------------------------------------------------------------------------
__device__ __forceinline__ float sig_raw(float x) {
    return __fdividef(1.0f, 1.0f + __expf(-x));
}
__device__ __forceinline__ float tanh_f(float x) {
    return fmaf(2.0f, sig_raw(2.0f * x), -1.0f);
}

__global__ __launch_bounds__(256, 2) void lstm_rec(
    const float* __restrict__ w_hh0,
    const float* __restrict__ w_ih1,
    const float* __restrict__ w_hh1,
    const float* __restrict__ b_ih1,
    const float* __restrict__ b_hh1,
    const float* __restrict__ w_lin,
    const float* __restrict__ b_lin,
    float* __restrict__ out)
{
    const int b0   = blockIdx.x * NB;
    const int tid  = threadIdx.x;
    const int wid  = tid >> 5;
    const int lane = tid & 31;
    const int layer = wid >> 2;
    const int wi    = wid & 3;
    const int j     = wi * 8 + (lane >> 2);
    const int q     = lane & 3;
    const bool jok  = (j < NHID);
    const int jc    = jok ? j : (NHID - 1);
    const int gr    = q * 30 + jc;

    __shared__ float4 sh_h0p[2][NHID];
    __shared__ float4 sh_hA[2][NHID];
    __shared__ float4 sh_hB[2][NHID];
    __shared__ float  sh_red[NB][32];

    uint64_t wp[NHID];
    float bias1 = 0.0f;
    if (layer == 0) {
#pragma unroll
        for (int k = 0; k < NHID; k++) {
            float w = w_hh0[gr * NHID + k];
            wp[k] = pack2(w, w);
        }
    } else {
#pragma unroll
        for (int k = 0; k < NHID; k++)
            wp[k] = pack2(w_ih1[gr * NHID + k], w_hh1[gr * NHID + k]);
        bias1 = b_ih1[gr] + b_hh1[gr];
    }

    float c = 0.0f, outacc = 0.0f;

    if (tid < NHID) {
        float4 z = make_float4(0.f, 0.f, 0.f, 0.f);
        sh_h0p[0][tid] = z; sh_h0p[1][tid] = z;
        sh_hA[0][tid]  = z; sh_hA[1][tid]  = z;
        sh_hB[0][tid]  = z; sh_hB[1][tid]  = z;
    }

    float xg_cur[NB];
    if (layer == 0) {
#pragma unroll
        for (int bb = 0; bb < NB; bb++)
            xg_cur[bb] = __ldg(&g_xg0[((size_t)(b0 + bb) * SEQLEN) * NGATE + gr]);
    }
    __syncthreads();

    const float a_scale = (q == 2) ? 2.0f : 1.0f;
    const float a_mult  = (q == 2) ? 2.0f : 1.0f;
    const float a_add   = (q == 2) ? -1.0f : 0.0f;

    for (int p = 0; p <= SEQLEN; p++) {
        const int wb = p & 1;
        const int rb = wb ^ 1;
        const bool active = (layer == 0) ? (p < SEQLEN) : (p >= 1);

        if (active) {
            float v0, v1, v2, v3;
            float wl = 0.0f;
            if (layer == 0) {
                uint64_t a01 = pack2(xg_cur[0], xg_cur[1]);
                uint64_t a23 = pack2(xg_cur[2], xg_cur[3]);
                if (p + 1 < SEQLEN) {
#pragma unroll
                    for (int bb = 0; bb < NB; bb++)
                        xg_cur[bb] = __ldg(&g_xg0[((size_t)(b0 + bb) * SEQLEN + p + 1) * NGATE + gr]);
                }
#pragma unroll
                for (int k = 0; k < NHID; k++) {
                    ulonglong2 h = *reinterpret_cast<const ulonglong2*>(&sh_h0p[rb][k]);
                    ffma2(a01, wp[k], h.x);
                    ffma2(a23, wp[k], h.y);
                }
                float2 p01 = unpack2(a01), p23 = unpack2(a23);
                v0 = p01.x; v1 = p01.y; v2 = p23.x; v3 = p23.y;
            } else {
                uint64_t a0 = pack2(bias1, 0.f);
                uint64_t a1 = a0, a2 = a0, a3 = a0;
                wl = __ldg(&w_lin[(p - 1) * NHID + jc]);
#pragma unroll
                for (int k = 0; k < NHID; k++) {
                    ulonglong2 hA = *reinterpret_cast<const ulonglong2*>(&sh_hA[rb][k]);
                    ulonglong2 hB = *reinterpret_cast<const ulonglong2*>(&sh_hB[rb][k]);
                    ffma2(a0, wp[k], hA.x);
                    ffma2(a1, wp[k], hA.y);
                    ffma2(a2, wp[k], hB.x);
                    ffma2(a3, wp[k], hB.y);
                }
                float2 r0 = unpack2(a0), r1 = unpack2(a1);
                float2 r2 = unpack2(a2), r3 = unpack2(a3);
                v0 = r0.x + r0.y; v1 = r1.x + r1.y;
                v2 = r2.x + r2.y; v3 = r3.x + r3.y;
            }
            v0 = fmaf(a_mult, sig_raw(v0 * a_scale), a_add);
            v1 = fmaf(a_mult, sig_raw(v1 * a_scale), a_add);
            v2 = fmaf(a_mult, sig_raw(v2 * a_scale), a_add);
            v3 = fmaf(a_mult, sig_raw(v3 * a_scale), a_add);

            float s1 = (q & 1) ? v0 : v1;
            float r1s = __shfl_xor_sync(0xffffffffu, s1, 1);
            float s2 = (q & 1) ? v2 : v3;
            float r2s = __shfl_xor_sync(0xffffffffu, s2, 1);
            float u0 = (q & 1) ? r1s : v0;
            float u1 = (q & 1) ? v1 : r1s;
            float u2 = (q & 1) ? r2s : v2;
            float u3 = (q & 1) ? v3 : r2s;
            float s3 = (q & 2) ? u0 : u2;
            float r3s = __shfl_xor_sync(0xffffffffu, s3, 2);
            float s4 = (q & 2) ? u1 : u3;
            float r4s = __shfl_xor_sync(0xffffffffu, s4, 2);
            float ti = (q & 2) ? r3s : u0;
            float tf = (q & 2) ? r4s : u1;
            float tg = (q & 2) ? u2 : r3s;
            float to = (q & 2) ? u3 : r4s;

            c = fmaf(tf, c, ti * tg);
            float h = to * tanh_f(c);
            if (jok) {
                float* pb = (q < 2) ? (float*)&sh_hA[wb][j] : (float*)&sh_hB[wb][j];
                pb[(q & 1) * 2 + layer] = h;
                if (layer == 0) {
                    ((float*)&sh_h0p[wb][j])[q] = h;
                } else {
                    outacc = fmaf(h, wl, outacc);
                }
            }
        }
        __syncthreads();
    }

    if (layer == 1 && jok) sh_red[q][j] = outacc;
    __syncthreads();
    if (tid < NB) {
        float s = b_lin[0];
#pragma unroll
        for (int jj = 0; jj < NHID; jj++) s += sh_red[tid][jj];
        out[b0 + tid] = s;
    }
}

// ---------------------------------------------------------------------------
// Entry point
// ---------------------------------------------------------------------------
extern "C" void kernel_launch(void* const* d_in, const int* in_sizes, int n_in,
                              void* d_out, int out_size)
{
    const float* x      = (const float*)d_in[0];
    const float* w_ih0  = (const float*)d_in[1];
    const float* w_hh0  = (const float*)d_in[2];
    const float* b_ih0  = (const float*)d_in[3];
    const float* b_hh0  = (const float*)d_in[4];
    const float* w_ih1  = (const float*)d_in[5];
    const float* w_hh1  = (const float*)d_in[6];
    const float* b_ih1  = (const float*)d_in[7];
    const float* b_hh1  = (const float*)d_in[8];
    const float* w_lin  = (const float*)d_in[9];
    const float* b_lin  = (const float*)d_in[10];
    float* out = (float*)d_out;

    wcvt<<<128, 256>>>(w_ih0);
    gemm_xg0_tc<<<MROWS / 128, 256>>>(x, b_ih0, b_hh0);
    lstm_rec<<<BATCH / NB, 256>>>(w_hh0, w_ih1, w_hh1, b_ih1, b_hh1, w_lin, b_lin, out);
}